// round 1
// baseline (speedup 1.0000x reference)
#include <cuda_runtime.h>

#define Bb 8
#define Nn 2048
#define Mm 2048
#define DIN 512
#define Hh 256

// ---------------- scratch (device globals; no allocs allowed) ----------------
__device__ float g_qs[(size_t)Bb*Nn*Hh];
__device__ float g_qe[(size_t)Bb*Nn*Hh];
__device__ float g_ks[(size_t)Bb*Mm*Hh];
__device__ float g_vs[(size_t)Bb*Mm*Hh];
__device__ float g_ke[(size_t)Bb*Mm*Hh];
__device__ float g_ve[(size_t)Bb*Mm*Hh];
__device__ float g_q2[Bb*Nn];
__device__ float g_k2[Bb*Mm];
__device__ float g_L[(size_t)Bb*Nn*Mm];   // logits, then probs in-place
__device__ float g_D[(size_t)Bb*Nn*Mm];   // electronic distance
__device__ float g_fused[(size_t)Bb*Nn*4*Hh];
__device__ float g_hbuf[(size_t)Bb*Nn*Hh];
__device__ float g_dsum[Bb];
__device__ float g_scale[Bb];

// ---------------- reduce helpers ----------------
__device__ __forceinline__ float warpRedSum(float v) {
#pragma unroll
    for (int o = 16; o > 0; o >>= 1) v += __shfl_xor_sync(0xffffffffu, v, o);
    return v;
}
__device__ __forceinline__ float warpRedMax(float v) {
#pragma unroll
    for (int o = 16; o > 0; o >>= 1) v = fmaxf(v, __shfl_xor_sync(0xffffffffu, v, o));
    return v;
}

// ---------------- generic SGEMM: C[Mr,Nc] = A[Mr,K] @ W[K,Nc] + bias, act ----
// block (16,16), tile 64x64, BK=16, 4x4 per thread
__global__ void sgemm_bias_kernel(const float* __restrict__ A,
                                  const float* __restrict__ W,
                                  const float* __restrict__ bias,
                                  float* __restrict__ C,
                                  int Mr, int K, int Nc, int act) {
    __shared__ float As[16][65];
    __shared__ float Bs[16][64];
    const int row0 = blockIdx.y * 64;
    const int col0 = blockIdx.x * 64;
    const int tid  = threadIdx.y * 16 + threadIdx.x;
    float acc[4][4] = {};
    for (int k0 = 0; k0 < K; k0 += 16) {
        for (int i = tid; i < 64 * 16; i += 256) {
            int r = i >> 4, c = i & 15;
            As[c][r] = A[(size_t)(row0 + r) * K + k0 + c];
        }
        for (int i = tid; i < 16 * 64; i += 256) {
            int r = i >> 6, c = i & 63;
            Bs[r][c] = W[(size_t)(k0 + r) * Nc + col0 + c];
        }
        __syncthreads();
#pragma unroll
        for (int k = 0; k < 16; k++) {
            float a[4], bb[4];
#pragma unroll
            for (int i = 0; i < 4; i++) a[i]  = As[k][threadIdx.y * 4 + i];
#pragma unroll
            for (int j = 0; j < 4; j++) bb[j] = Bs[k][threadIdx.x * 4 + j];
#pragma unroll
            for (int i = 0; i < 4; i++)
#pragma unroll
                for (int j = 0; j < 4; j++)
                    acc[i][j] = fmaf(a[i], bb[j], acc[i][j]);
        }
        __syncthreads();
    }
#pragma unroll
    for (int i = 0; i < 4; i++) {
        int r = row0 + threadIdx.y * 4 + i;
#pragma unroll
        for (int j = 0; j < 4; j++) {
            int c = col0 + threadIdx.x * 4 + j;
            float v = acc[i][j] + bias[c];
            if (act == 1) v = v / (1.0f + __expf(-v));  // silu
            C[(size_t)r * Nc + c] = v;
        }
    }
}

// ---------------- row sum of squares (row length == 256 == blockDim) --------
__global__ void rowsumsq_kernel(const float* __restrict__ src, float* __restrict__ dst) {
    const int row = blockIdx.x;
    float v = src[(size_t)row * Hh + threadIdx.x];
    v *= v;
    __shared__ float sh[8];
    int lane = threadIdx.x & 31, wid = threadIdx.x >> 5;
    float w = warpRedSum(v);
    if (lane == 0) sh[wid] = w;
    __syncthreads();
    if (wid == 0) {
        float t = (lane < 8) ? sh[lane] : 0.0f;
        t = warpRedSum(t);
        if (lane == 0) dst[row] = t;
    }
}

__global__ void zero_dsum_kernel() {
    if (threadIdx.x < Bb) g_dsum[threadIdx.x] = 0.0f;
}
__global__ void finalize_scale_kernel() {
    if (threadIdx.x < Bb)
        g_scale[threadIdx.x] =
            fmaxf(g_dsum[threadIdx.x] * (1.0f / ((float)Nn * (float)Mm)), 1e-4f);
}

// ---------------- logits: dual GEMM over H, + dist + pi_mask + dist-sum -----
// grid (M/64, N/64, B), block (16,16)
__global__ void logits_kernel(const float* __restrict__ pi_star,
                              const float* __restrict__ gamma_p) {
    const int b  = blockIdx.z;
    const int n0 = blockIdx.y * 64;
    const int m0 = blockIdx.x * 64;
    __shared__ float Qs[16][65], Qe[16][65], Ks[16][65], Ke[16][65];
    const int tid = threadIdx.y * 16 + threadIdx.x;
    float accS[4][4] = {}, accE[4][4] = {};
    const float* qs = g_qs + (size_t)(b * Nn + n0) * Hh;
    const float* qe = g_qe + (size_t)(b * Nn + n0) * Hh;
    const float* ks = g_ks + (size_t)(b * Mm + m0) * Hh;
    const float* ke = g_ke + (size_t)(b * Mm + m0) * Hh;
    for (int k0 = 0; k0 < Hh; k0 += 16) {
        for (int i = tid; i < 64 * 16; i += 256) {
            int r = i >> 4, c = i & 15;
            size_t off = (size_t)r * Hh + k0 + c;
            Qs[c][r] = qs[off];
            Qe[c][r] = qe[off];
            Ks[c][r] = ks[off];
            Ke[c][r] = ke[off];
        }
        __syncthreads();
#pragma unroll
        for (int k = 0; k < 16; k++) {
            float aS[4], aE[4], bS[4], bE[4];
#pragma unroll
            for (int i = 0; i < 4; i++) {
                aS[i] = Qs[k][threadIdx.y * 4 + i];
                aE[i] = Qe[k][threadIdx.y * 4 + i];
            }
#pragma unroll
            for (int j = 0; j < 4; j++) {
                bS[j] = Ks[k][threadIdx.x * 4 + j];
                bE[j] = Ke[k][threadIdx.x * 4 + j];
            }
#pragma unroll
            for (int i = 0; i < 4; i++)
#pragma unroll
                for (int j = 0; j < 4; j++) {
                    accS[i][j] = fmaf(aS[i], bS[j], accS[i][j]);
                    accE[i][j] = fmaf(aE[i], bE[j], accE[i][j]);
                }
        }
        __syncthreads();
    }
    const float g = gamma_p[0];
    float sumd = 0.0f;
#pragma unroll
    for (int i = 0; i < 4; i++) {
        const int n = n0 + threadIdx.y * 4 + i;
        const float q2v = g_q2[b * Nn + n];
        const size_t rowbase = ((size_t)b * Nn + n) * Mm;
#pragma unroll
        for (int j = 0; j < 4; j++) {
            const int m = m0 + threadIdx.x * 4 + j;
            float d2 = q2v + g_k2[b * Mm + m] - 2.0f * accE[i][j];
            float dist = sqrtf(fmaxf(d2, 1e-12f));
            sumd += dist;
            g_D[rowbase + m] = dist;
            float ps = pi_star[rowbase + m];
            g_L[rowbase + m] = accS[i][j] * 0.0625f + g * __logf(fmaxf(ps, 1e-9f));
        }
    }
    __shared__ float red[256];
    red[tid] = sumd;
    __syncthreads();
    for (int s = 128; s > 0; s >>= 1) {
        if (tid < s) red[tid] += red[tid + s];
        __syncthreads();
    }
    if (tid == 0) atomicAdd(&g_dsum[b], red[0]);
}

// ---------------- softmax: one block (256 thr) per row, 8 vals/thread -------
__global__ void softmax_kernel(const float* __restrict__ ew_p) {
    const int row = blockIdx.x;           // b*N + n
    const int b   = row / Nn;
    const float invsc = ew_p[0] / g_scale[b];
    const size_t base = (size_t)row * Mm;
    float v[8];
    float mx = -1e30f;
#pragma unroll
    for (int t = 0; t < 8; t++) {
        int idx = t * 256 + threadIdx.x;
        v[t] = g_L[base + idx] - g_D[base + idx] * invsc;
        mx = fmaxf(mx, v[t]);
    }
    __shared__ float sh[8];
    __shared__ float bc;
    int lane = threadIdx.x & 31, wid = threadIdx.x >> 5;
    float wm = warpRedMax(mx);
    if (lane == 0) sh[wid] = wm;
    __syncthreads();
    if (wid == 0) {
        float t = (lane < 8) ? sh[lane] : -1e30f;
        t = warpRedMax(t);
        if (lane == 0) bc = t;
    }
    __syncthreads();
    mx = bc;
    float sum = 0.0f;
#pragma unroll
    for (int t = 0; t < 8; t++) {
        v[t] = __expf(v[t] - mx);
        sum += v[t];
    }
    __syncthreads();  // sh reuse
    float ws = warpRedSum(sum);
    if (lane == 0) sh[wid] = ws;
    __syncthreads();
    if (wid == 0) {
        float t = (lane < 8) ? sh[lane] : 0.0f;
        t = warpRedSum(t);
        if (lane == 0) bc = t;
    }
    __syncthreads();
    const float inv = 1.0f / bc;
#pragma unroll
    for (int t = 0; t < 8; t++) {
        int idx = t * 256 + threadIdx.x;
        g_L[base + idx] = v[t] * inv;  // probs in place
    }
}

// ---------------- ctx: dual GEMM attn@Vs / attn@Ve -> fused features --------
// grid (H/64, N/64, B), block (16,16)
__global__ void ctx_kernel() {
    const int b  = blockIdx.z;
    const int n0 = blockIdx.y * 64;
    const int h0 = blockIdx.x * 64;
    __shared__ float Ps[16][65];
    __shared__ float Vs[16][64], Ve[16][64];
    const int tid = threadIdx.y * 16 + threadIdx.x;
    float accS[4][4] = {}, accE[4][4] = {};
    for (int m0 = 0; m0 < Mm; m0 += 16) {
        for (int i = tid; i < 64 * 16; i += 256) {
            int r = i >> 4, c = i & 15;
            Ps[c][r] = g_L[((size_t)b * Nn + n0 + r) * Mm + m0 + c];
        }
        for (int i = tid; i < 16 * 64; i += 256) {
            int r = i >> 6, c = i & 63;
            size_t off = ((size_t)b * Mm + m0 + r) * Hh + h0 + c;
            Vs[r][c] = g_vs[off];
            Ve[r][c] = g_ve[off];
        }
        __syncthreads();
#pragma unroll
        for (int k = 0; k < 16; k++) {
            float a[4], bS[4], bE[4];
#pragma unroll
            for (int i = 0; i < 4; i++) a[i] = Ps[k][threadIdx.y * 4 + i];
#pragma unroll
            for (int j = 0; j < 4; j++) {
                bS[j] = Vs[k][threadIdx.x * 4 + j];
                bE[j] = Ve[k][threadIdx.x * 4 + j];
            }
#pragma unroll
            for (int i = 0; i < 4; i++)
#pragma unroll
                for (int j = 0; j < 4; j++) {
                    accS[i][j] = fmaf(a[i], bS[j], accS[i][j]);
                    accE[i][j] = fmaf(a[i], bE[j], accE[i][j]);
                }
        }
        __syncthreads();
    }
#pragma unroll
    for (int i = 0; i < 4; i++) {
        const int n = n0 + threadIdx.y * 4 + i;
        const size_t fb = ((size_t)b * Nn + n) * (4 * Hh);
#pragma unroll
        for (int j = 0; j < 4; j++) {
            const int h = h0 + threadIdx.x * 4 + j;
            float cs = accS[i][j], ce = accE[i][j];
            g_fused[fb + h]            = cs;
            g_fused[fb + Hh + h]       = ce;
            g_fused[fb + 2 * Hh + h]   = cs - ce;
            g_fused[fb + 3 * Hh + h]   = cs * ce;
        }
    }
}

// ---------------- launch ----------------
extern "C" void kernel_launch(void* const* d_in, const int* in_sizes, int n_in,
                              void* d_out, int out_size) {
    const float* q_fp  = (const float*)d_in[0];
    const float* v_ret = (const float*)d_in[1];
    const float* pi    = (const float*)d_in[2];
    const float* Wqs = (const float*)d_in[3];  const float* bqs = (const float*)d_in[4];
    const float* Wks = (const float*)d_in[5];  const float* bks = (const float*)d_in[6];
    const float* Wvs = (const float*)d_in[7];  const float* bvs = (const float*)d_in[8];
    const float* Wqe = (const float*)d_in[9];  const float* bqe = (const float*)d_in[10];
    const float* Wke = (const float*)d_in[11]; const float* bke = (const float*)d_in[12];
    const float* Wve = (const float*)d_in[13]; const float* bve = (const float*)d_in[14];
    const float* W1  = (const float*)d_in[15]; const float* b1  = (const float*)d_in[16];
    const float* W2  = (const float*)d_in[17]; const float* b2  = (const float*)d_in[18];
    const float* gamma = (const float*)d_in[19];
    const float* ew    = (const float*)d_in[20];
    float* out = (float*)d_out;

    float *qs_p, *qe_p, *ks_p, *vs_p, *ke_p, *ve_p, *q2_p, *k2_p, *fused_p, *h_p;
    cudaGetSymbolAddress((void**)&qs_p, g_qs);
    cudaGetSymbolAddress((void**)&qe_p, g_qe);
    cudaGetSymbolAddress((void**)&ks_p, g_ks);
    cudaGetSymbolAddress((void**)&vs_p, g_vs);
    cudaGetSymbolAddress((void**)&ke_p, g_ke);
    cudaGetSymbolAddress((void**)&ve_p, g_ve);
    cudaGetSymbolAddress((void**)&q2_p, g_q2);
    cudaGetSymbolAddress((void**)&k2_p, g_k2);
    cudaGetSymbolAddress((void**)&fused_p, g_fused);
    cudaGetSymbolAddress((void**)&h_p, g_hbuf);

    dim3 blk(16, 16);
    dim3 gproj(Hh / 64, (Bb * Nn) / 64);  // (4, 256)
    sgemm_bias_kernel<<<gproj, blk>>>(q_fp,  Wqs, bqs, qs_p, Bb * Nn, DIN, Hh, 0);
    sgemm_bias_kernel<<<gproj, blk>>>(q_fp,  Wqe, bqe, qe_p, Bb * Nn, DIN, Hh, 0);
    sgemm_bias_kernel<<<gproj, blk>>>(v_ret, Wks, bks, ks_p, Bb * Mm, DIN, Hh, 0);
    sgemm_bias_kernel<<<gproj, blk>>>(v_ret, Wvs, bvs, vs_p, Bb * Mm, DIN, Hh, 0);
    sgemm_bias_kernel<<<gproj, blk>>>(v_ret, Wke, bke, ke_p, Bb * Mm, DIN, Hh, 0);
    sgemm_bias_kernel<<<gproj, blk>>>(v_ret, Wve, bve, ve_p, Bb * Mm, DIN, Hh, 0);

    rowsumsq_kernel<<<Bb * Nn, 256>>>(qe_p, q2_p);
    rowsumsq_kernel<<<Bb * Mm, 256>>>(ke_p, k2_p);

    zero_dsum_kernel<<<1, 32>>>();
    dim3 glog(Mm / 64, Nn / 64, Bb);
    logits_kernel<<<glog, blk>>>(pi, gamma);
    finalize_scale_kernel<<<1, 32>>>();

    softmax_kernel<<<Bb * Nn, 256>>>(ew);

    dim3 gctx(Hh / 64, Nn / 64, Bb);
    ctx_kernel<<<gctx, blk>>>();

    dim3 gmlp(Hh / 64, (Bb * Nn) / 64);
    sgemm_bias_kernel<<<gmlp, blk>>>(fused_p, W1, b1, h_p, Bb * Nn, 4 * Hh, Hh, 1);
    sgemm_bias_kernel<<<gmlp, blk>>>(h_p,     W2, b2, out, Bb * Nn, Hh,     Hh, 0);
}

// round 2
// speedup vs baseline: 1.4175x; 1.4175x over previous
#include <cuda_runtime.h>
#include <cstdint>

#define Bb 8
#define Nn 2048
#define Mm 2048
#define DIN 512
#define Hh 256

// ---------------- scratch (device globals; no allocs allowed) ----------------
__device__ float g_qs[(size_t)Bb*Nn*Hh];
__device__ float g_qe[(size_t)Bb*Nn*Hh];
__device__ float g_ks[(size_t)Bb*Mm*Hh];
__device__ float g_vs[(size_t)Bb*Mm*Hh];
__device__ float g_ke[(size_t)Bb*Mm*Hh];
__device__ float g_ve[(size_t)Bb*Mm*Hh];
__device__ float g_q2[Bb*Nn];
__device__ float g_k2[Bb*Mm];
__device__ float g_L[(size_t)Bb*Nn*Mm];   // logits, then probs in-place
__device__ float g_D[(size_t)Bb*Nn*Mm];   // electronic distance
__device__ float g_fused[(size_t)Bb*Nn*4*Hh];
__device__ float g_hbuf[(size_t)Bb*Nn*Hh];
__device__ float g_dsum[Bb];
__device__ float g_scale[Bb];

// ---------------- tf32 helpers ----------------
__device__ __forceinline__ uint32_t f2tf(float x) {
    uint32_t u;
    asm("cvt.rna.tf32.f32 %0, %1;" : "=r"(u) : "f"(x));
    return u;
}
__device__ __forceinline__ void split_tf32(float x, uint32_t& h, uint32_t& l) {
    h = f2tf(x);
    l = f2tf(x - __uint_as_float(h));
}
__device__ __forceinline__ void mma8(float* d, const uint32_t* a, uint32_t b0, uint32_t b1) {
    asm volatile(
        "mma.sync.aligned.m16n8k8.row.col.f32.tf32.tf32.f32 "
        "{%0,%1,%2,%3}, {%4,%5,%6,%7}, {%8,%9}, {%0,%1,%2,%3};\n"
        : "+f"(d[0]), "+f"(d[1]), "+f"(d[2]), "+f"(d[3])
        : "r"(a[0]), "r"(a[1]), "r"(a[2]), "r"(a[3]), "r"(b0), "r"(b1));
}

__device__ __forceinline__ float warpRedSum(float v) {
#pragma unroll
    for (int o = 16; o > 0; o >>= 1) v += __shfl_xor_sync(0xffffffffu, v, o);
    return v;
}
__device__ __forceinline__ float warpRedMax(float v) {
#pragma unroll
    for (int o = 16; o > 0; o >>= 1) v = fmaxf(v, __shfl_xor_sync(0xffffffffu, v, o));
    return v;
}

// =============================================================================
// Generic 3xTF32 GEMM:  C[R,Nc] = A[R,K] @ W[K,Nc] + bias, optional SiLU.
// Block tile 128x128, BK=16, 8 warps (4x2), warp tile 32x64.
// =============================================================================
__global__ __launch_bounds__(256) void gemm3_kernel(
    const float* __restrict__ A, const float* __restrict__ W,
    const float* __restrict__ bias, float* __restrict__ C,
    int K, int Nc, int act)
{
    __shared__ uint32_t AsH[128][20], AsL[128][20];   // [m][k], pad 20: conflict-free frags
    __shared__ uint32_t BsH[16][136], BsL[16][136];   // [k][n], pad 136: conflict-free frags
    const int row0 = blockIdx.y * 128;
    const int col0 = blockIdx.x * 128;
    const int tid  = threadIdx.x;
    const int lane = tid & 31, warp = tid >> 5;
    const int wR = warp >> 1, wC = warp & 1;

    float acc[2][8][4];
#pragma unroll
    for (int i = 0; i < 2; i++)
#pragma unroll
        for (int j = 0; j < 8; j++)
#pragma unroll
            for (int q = 0; q < 4; q++) acc[i][j][q] = 0.0f;

    for (int k0 = 0; k0 < K; k0 += 16) {
#pragma unroll
        for (int it = 0; it < 2; it++) {
            int i = tid + it * 256;              // [0,512)
            int r = i >> 2, c4 = (i & 3) * 4;
            float4 v = *(const float4*)&A[(size_t)(row0 + r) * K + k0 + c4];
            uint32_t h, l;
            split_tf32(v.x, h, l); AsH[r][c4 + 0] = h; AsL[r][c4 + 0] = l;
            split_tf32(v.y, h, l); AsH[r][c4 + 1] = h; AsL[r][c4 + 1] = l;
            split_tf32(v.z, h, l); AsH[r][c4 + 2] = h; AsL[r][c4 + 2] = l;
            split_tf32(v.w, h, l); AsH[r][c4 + 3] = h; AsL[r][c4 + 3] = l;
        }
#pragma unroll
        for (int it = 0; it < 2; it++) {
            int i = tid + it * 256;              // [0,512)
            int r = i >> 5, c4 = (i & 31) * 4;
            float4 v = *(const float4*)&W[(size_t)(k0 + r) * Nc + col0 + c4];
            uint32_t h, l;
            split_tf32(v.x, h, l); BsH[r][c4 + 0] = h; BsL[r][c4 + 0] = l;
            split_tf32(v.y, h, l); BsH[r][c4 + 1] = h; BsL[r][c4 + 1] = l;
            split_tf32(v.z, h, l); BsH[r][c4 + 2] = h; BsL[r][c4 + 2] = l;
            split_tf32(v.w, h, l); BsH[r][c4 + 3] = h; BsL[r][c4 + 3] = l;
        }
        __syncthreads();
#pragma unroll
        for (int ks = 0; ks < 2; ks++) {
            const int kb = ks * 8;
            const int kk = kb + (lane & 3);
            uint32_t aH[2][4], aL[2][4];
#pragma unroll
            for (int i = 0; i < 2; i++) {
                int m = wR * 32 + i * 16 + (lane >> 2);
                aH[i][0] = AsH[m][kk];     aH[i][1] = AsH[m + 8][kk];
                aH[i][2] = AsH[m][kk + 4]; aH[i][3] = AsH[m + 8][kk + 4];
                aL[i][0] = AsL[m][kk];     aL[i][1] = AsL[m + 8][kk];
                aL[i][2] = AsL[m][kk + 4]; aL[i][3] = AsL[m + 8][kk + 4];
            }
#pragma unroll
            for (int j = 0; j < 8; j++) {
                int n = wC * 64 + j * 8 + (lane >> 2);
                uint32_t bh0 = BsH[kb + (lane & 3)][n];
                uint32_t bh1 = BsH[kb + 4 + (lane & 3)][n];
                uint32_t bl0 = BsL[kb + (lane & 3)][n];
                uint32_t bl1 = BsL[kb + 4 + (lane & 3)][n];
#pragma unroll
                for (int i = 0; i < 2; i++) {
                    mma8(acc[i][j], aH[i], bh0, bh1);
                    mma8(acc[i][j], aH[i], bl0, bl1);
                    mma8(acc[i][j], aL[i], bh0, bh1);
                }
            }
        }
        __syncthreads();
    }
    // epilogue
#pragma unroll
    for (int i = 0; i < 2; i++) {
        int r = row0 + wR * 32 + i * 16 + (lane >> 2);
#pragma unroll
        for (int j = 0; j < 8; j++) {
            int c = col0 + wC * 64 + j * 8 + 2 * (lane & 3);
            float b0 = bias[c], b1 = bias[c + 1];
            float v0 = acc[i][j][0] + b0, v1 = acc[i][j][1] + b1;
            float v2 = acc[i][j][2] + b0, v3 = acc[i][j][3] + b1;
            if (act) {
                v0 = v0 / (1.0f + __expf(-v0));
                v1 = v1 / (1.0f + __expf(-v1));
                v2 = v2 / (1.0f + __expf(-v2));
                v3 = v3 / (1.0f + __expf(-v3));
            }
            *(float2*)&C[(size_t)r * Nc + c]       = make_float2(v0, v1);
            *(float2*)&C[(size_t)(r + 8) * Nc + c] = make_float2(v2, v3);
        }
    }
}

// =============================================================================
// Logits: dual 3xTF32 NT GEMM (Qs@Ks^T, Qe@Ke^T) + dist/pi epilogue + dist-sum.
// Block tile 128(n) x 64(m), BK=8, 8 warps (4x2), warp tile 32x32.
// =============================================================================
__global__ __launch_bounds__(256) void logits3_kernel(
    const float* __restrict__ pi_star, const float* __restrict__ gamma_p)
{
    __shared__ uint32_t QsH[128][12], QsL[128][12], QeH[128][12], QeL[128][12];
    __shared__ uint32_t KsH[64][12],  KsL[64][12],  KeH[64][12],  KeL[64][12];
    __shared__ float red[256];

    const int b  = blockIdx.z;
    const int n0 = blockIdx.y * 128;
    const int m0 = blockIdx.x * 64;
    const int tid = threadIdx.x;
    const int lane = tid & 31, warp = tid >> 5;
    const int wR = warp >> 1, wC = warp & 1;

    const float* qs = g_qs + (size_t)(b * Nn + n0) * Hh;
    const float* qe = g_qe + (size_t)(b * Nn + n0) * Hh;
    const float* ks = g_ks + (size_t)(b * Mm + m0) * Hh;
    const float* ke = g_ke + (size_t)(b * Mm + m0) * Hh;

    float accS[2][4][4], accE[2][4][4];
#pragma unroll
    for (int i = 0; i < 2; i++)
#pragma unroll
        for (int j = 0; j < 4; j++)
#pragma unroll
            for (int q = 0; q < 4; q++) { accS[i][j][q] = 0.0f; accE[i][j][q] = 0.0f; }

    for (int k0 = 0; k0 < Hh; k0 += 8) {
        {   // Q tiles: one float4 per thread per array
            int r = tid >> 1, c4 = (tid & 1) * 4;
            float4 v = *(const float4*)&qs[(size_t)r * Hh + k0 + c4];
            uint32_t h, l;
            split_tf32(v.x, h, l); QsH[r][c4 + 0] = h; QsL[r][c4 + 0] = l;
            split_tf32(v.y, h, l); QsH[r][c4 + 1] = h; QsL[r][c4 + 1] = l;
            split_tf32(v.z, h, l); QsH[r][c4 + 2] = h; QsL[r][c4 + 2] = l;
            split_tf32(v.w, h, l); QsH[r][c4 + 3] = h; QsL[r][c4 + 3] = l;
            v = *(const float4*)&qe[(size_t)r * Hh + k0 + c4];
            split_tf32(v.x, h, l); QeH[r][c4 + 0] = h; QeL[r][c4 + 0] = l;
            split_tf32(v.y, h, l); QeH[r][c4 + 1] = h; QeL[r][c4 + 1] = l;
            split_tf32(v.z, h, l); QeH[r][c4 + 2] = h; QeL[r][c4 + 2] = l;
            split_tf32(v.w, h, l); QeH[r][c4 + 3] = h; QeL[r][c4 + 3] = l;
        }
        {   // K tiles: half the threads each
            int t = tid & 127;
            int r = t >> 1, c4 = (t & 1) * 4;
            const float* src = (tid < 128) ? ks : ke;
            float4 v = *(const float4*)&src[(size_t)r * Hh + k0 + c4];
            uint32_t h, l;
            if (tid < 128) {
                split_tf32(v.x, h, l); KsH[r][c4 + 0] = h; KsL[r][c4 + 0] = l;
                split_tf32(v.y, h, l); KsH[r][c4 + 1] = h; KsL[r][c4 + 1] = l;
                split_tf32(v.z, h, l); KsH[r][c4 + 2] = h; KsL[r][c4 + 2] = l;
                split_tf32(v.w, h, l); KsH[r][c4 + 3] = h; KsL[r][c4 + 3] = l;
            } else {
                split_tf32(v.x, h, l); KeH[r][c4 + 0] = h; KeL[r][c4 + 0] = l;
                split_tf32(v.y, h, l); KeH[r][c4 + 1] = h; KeL[r][c4 + 1] = l;
                split_tf32(v.z, h, l); KeH[r][c4 + 2] = h; KeL[r][c4 + 2] = l;
                split_tf32(v.w, h, l); KeH[r][c4 + 3] = h; KeL[r][c4 + 3] = l;
            }
        }
        __syncthreads();
        const int kk = lane & 3;
        uint32_t asH[2][4], asL[2][4], aeH[2][4], aeL[2][4];
#pragma unroll
        for (int i = 0; i < 2; i++) {
            int m = wR * 32 + i * 16 + (lane >> 2);
            asH[i][0] = QsH[m][kk];     asH[i][1] = QsH[m + 8][kk];
            asH[i][2] = QsH[m][kk + 4]; asH[i][3] = QsH[m + 8][kk + 4];
            asL[i][0] = QsL[m][kk];     asL[i][1] = QsL[m + 8][kk];
            asL[i][2] = QsL[m][kk + 4]; asL[i][3] = QsL[m + 8][kk + 4];
            aeH[i][0] = QeH[m][kk];     aeH[i][1] = QeH[m + 8][kk];
            aeH[i][2] = QeH[m][kk + 4]; aeH[i][3] = QeH[m + 8][kk + 4];
            aeL[i][0] = QeL[m][kk];     aeL[i][1] = QeL[m + 8][kk];
            aeL[i][2] = QeL[m][kk + 4]; aeL[i][3] = QeL[m + 8][kk + 4];
        }
#pragma unroll
        for (int j = 0; j < 4; j++) {
            int n = wC * 32 + j * 8 + (lane >> 2);
            uint32_t bsh0 = KsH[n][kk], bsh1 = KsH[n][kk + 4];
            uint32_t bsl0 = KsL[n][kk], bsl1 = KsL[n][kk + 4];
            uint32_t beh0 = KeH[n][kk], beh1 = KeH[n][kk + 4];
            uint32_t bel0 = KeL[n][kk], bel1 = KeL[n][kk + 4];
#pragma unroll
            for (int i = 0; i < 2; i++) {
                mma8(accS[i][j], asH[i], bsh0, bsh1);
                mma8(accS[i][j], asH[i], bsl0, bsl1);
                mma8(accS[i][j], asL[i], bsh0, bsh1);
                mma8(accE[i][j], aeH[i], beh0, beh1);
                mma8(accE[i][j], aeH[i], bel0, bel1);
                mma8(accE[i][j], aeL[i], beh0, beh1);
            }
        }
        __syncthreads();
    }

    const float g = gamma_p[0];
    float sumd = 0.0f;
#pragma unroll
    for (int i = 0; i < 2; i++) {
        int n_lo = n0 + wR * 32 + i * 16 + (lane >> 2);
        float q2a = g_q2[b * Nn + n_lo];
        float q2b = g_q2[b * Nn + n_lo + 8];
#pragma unroll
        for (int j = 0; j < 4; j++) {
            int m = m0 + wC * 32 + j * 8 + 2 * (lane & 3);
            float k2a = g_k2[b * Mm + m], k2b = g_k2[b * Mm + m + 1];
            // row n_lo (c0,c1)
            size_t base0 = ((size_t)b * Nn + n_lo) * Mm + m;
            float2 piv = *(const float2*)&pi_star[base0];
            float d0 = sqrtf(fmaxf(q2a + k2a - 2.0f * accE[i][j][0], 1e-12f));
            float d1 = sqrtf(fmaxf(q2a + k2b - 2.0f * accE[i][j][1], 1e-12f));
            sumd += d0 + d1;
            *(float2*)&g_D[base0] = make_float2(d0, d1);
            float L0 = accS[i][j][0] * 0.0625f + g * __logf(fmaxf(piv.x, 1e-9f));
            float L1 = accS[i][j][1] * 0.0625f + g * __logf(fmaxf(piv.y, 1e-9f));
            *(float2*)&g_L[base0] = make_float2(L0, L1);
            // row n_lo + 8 (c2,c3)
            size_t base1 = ((size_t)b * Nn + n_lo + 8) * Mm + m;
            piv = *(const float2*)&pi_star[base1];
            float d2v = sqrtf(fmaxf(q2b + k2a - 2.0f * accE[i][j][2], 1e-12f));
            float d3v = sqrtf(fmaxf(q2b + k2b - 2.0f * accE[i][j][3], 1e-12f));
            sumd += d2v + d3v;
            *(float2*)&g_D[base1] = make_float2(d2v, d3v);
            float L2 = accS[i][j][2] * 0.0625f + g * __logf(fmaxf(piv.x, 1e-9f));
            float L3 = accS[i][j][3] * 0.0625f + g * __logf(fmaxf(piv.y, 1e-9f));
            *(float2*)&g_L[base1] = make_float2(L2, L3);
        }
    }
    red[tid] = sumd;
    __syncthreads();
    for (int s = 128; s > 0; s >>= 1) {
        if (tid < s) red[tid] += red[tid + s];
        __syncthreads();
    }
    if (tid == 0) atomicAdd(&g_dsum[b], red[0]);
}

// =============================================================================
// Ctx: dual 3xTF32 NN GEMM attn@Vs / attn@Ve -> fused features.
// Block tile 128(n) x 64(h), BK=16, 8 warps (4x2), warp tile 32x32.
// =============================================================================
__global__ __launch_bounds__(256) void ctx3_kernel()
{
    __shared__ uint32_t PH[128][20], PL[128][20];
    __shared__ uint32_t VsH[16][72], VsL[16][72], VeH[16][72], VeL[16][72];

    const int b  = blockIdx.z;
    const int n0 = blockIdx.y * 128;
    const int h0 = blockIdx.x * 64;
    const int tid = threadIdx.x;
    const int lane = tid & 31, warp = tid >> 5;
    const int wR = warp >> 1, wC = warp & 1;

    float accS[2][4][4], accE[2][4][4];
#pragma unroll
    for (int i = 0; i < 2; i++)
#pragma unroll
        for (int j = 0; j < 4; j++)
#pragma unroll
            for (int q = 0; q < 4; q++) { accS[i][j][q] = 0.0f; accE[i][j][q] = 0.0f; }

    for (int m0 = 0; m0 < Mm; m0 += 16) {
#pragma unroll
        for (int it = 0; it < 2; it++) {
            int i = tid + it * 256;
            int r = i >> 2, c4 = (i & 3) * 4;
            float4 v = *(const float4*)&g_L[((size_t)b * Nn + n0 + r) * Mm + m0 + c4];
            uint32_t h, l;
            split_tf32(v.x, h, l); PH[r][c4 + 0] = h; PL[r][c4 + 0] = l;
            split_tf32(v.y, h, l); PH[r][c4 + 1] = h; PL[r][c4 + 1] = l;
            split_tf32(v.z, h, l); PH[r][c4 + 2] = h; PL[r][c4 + 2] = l;
            split_tf32(v.w, h, l); PH[r][c4 + 3] = h; PL[r][c4 + 3] = l;
        }
        {
            int r = tid >> 4, c4 = (tid & 15) * 4;
            size_t off = ((size_t)b * Mm + m0 + r) * Hh + h0 + c4;
            float4 v = *(const float4*)&g_vs[off];
            uint32_t h, l;
            split_tf32(v.x, h, l); VsH[r][c4 + 0] = h; VsL[r][c4 + 0] = l;
            split_tf32(v.y, h, l); VsH[r][c4 + 1] = h; VsL[r][c4 + 1] = l;
            split_tf32(v.z, h, l); VsH[r][c4 + 2] = h; VsL[r][c4 + 2] = l;
            split_tf32(v.w, h, l); VsH[r][c4 + 3] = h; VsL[r][c4 + 3] = l;
            v = *(const float4*)&g_ve[off];
            split_tf32(v.x, h, l); VeH[r][c4 + 0] = h; VeL[r][c4 + 0] = l;
            split_tf32(v.y, h, l); VeH[r][c4 + 1] = h; VeL[r][c4 + 1] = l;
            split_tf32(v.z, h, l); VeH[r][c4 + 2] = h; VeL[r][c4 + 2] = l;
            split_tf32(v.w, h, l); VeH[r][c4 + 3] = h; VeL[r][c4 + 3] = l;
        }
        __syncthreads();
#pragma unroll
        for (int ks = 0; ks < 2; ks++) {
            const int kb = ks * 8;
            const int kk = kb + (lane & 3);
            uint32_t aH[2][4], aL[2][4];
#pragma unroll
            for (int i = 0; i < 2; i++) {
                int m = wR * 32 + i * 16 + (lane >> 2);
                aH[i][0] = PH[m][kk];     aH[i][1] = PH[m + 8][kk];
                aH[i][2] = PH[m][kk + 4]; aH[i][3] = PH[m + 8][kk + 4];
                aL[i][0] = PL[m][kk];     aL[i][1] = PL[m + 8][kk];
                aL[i][2] = PL[m][kk + 4]; aL[i][3] = PL[m + 8][kk + 4];
            }
#pragma unroll
            for (int j = 0; j < 4; j++) {
                int n = wC * 32 + j * 8 + (lane >> 2);
                uint32_t sh0 = VsH[kb + (lane & 3)][n], sh1 = VsH[kb + 4 + (lane & 3)][n];
                uint32_t sl0 = VsL[kb + (lane & 3)][n], sl1 = VsL[kb + 4 + (lane & 3)][n];
                uint32_t eh0 = VeH[kb + (lane & 3)][n], eh1 = VeH[kb + 4 + (lane & 3)][n];
                uint32_t el0 = VeL[kb + (lane & 3)][n], el1 = VeL[kb + 4 + (lane & 3)][n];
#pragma unroll
                for (int i = 0; i < 2; i++) {
                    mma8(accS[i][j], aH[i], sh0, sh1);
                    mma8(accS[i][j], aH[i], sl0, sl1);
                    mma8(accS[i][j], aL[i], sh0, sh1);
                    mma8(accE[i][j], aH[i], eh0, eh1);
                    mma8(accE[i][j], aH[i], el0, el1);
                    mma8(accE[i][j], aL[i], eh0, eh1);
                }
            }
        }
        __syncthreads();
    }
#pragma unroll
    for (int i = 0; i < 2; i++) {
        int n_lo = n0 + wR * 32 + i * 16 + (lane >> 2);
#pragma unroll
        for (int j = 0; j < 4; j++) {
            int h = h0 + wC * 32 + j * 8 + 2 * (lane & 3);
#pragma unroll
            for (int half = 0; half < 2; half++) {
                int n = n_lo + half * 8;
                float cs0 = accS[i][j][half * 2 + 0], cs1 = accS[i][j][half * 2 + 1];
                float ce0 = accE[i][j][half * 2 + 0], ce1 = accE[i][j][half * 2 + 1];
                size_t fb = ((size_t)b * Nn + n) * (4 * Hh);
                *(float2*)&g_fused[fb + h]            = make_float2(cs0, cs1);
                *(float2*)&g_fused[fb + Hh + h]       = make_float2(ce0, ce1);
                *(float2*)&g_fused[fb + 2 * Hh + h]   = make_float2(cs0 - ce0, cs1 - ce1);
                *(float2*)&g_fused[fb + 3 * Hh + h]   = make_float2(cs0 * ce0, cs1 * ce1);
            }
        }
    }
}

// ---------------- small kernels (unchanged from R1) ----------------
__global__ void rowsumsq_kernel(const float* __restrict__ src, float* __restrict__ dst) {
    const int row = blockIdx.x;
    float v = src[(size_t)row * Hh + threadIdx.x];
    v *= v;
    __shared__ float sh[8];
    int lane = threadIdx.x & 31, wid = threadIdx.x >> 5;
    float w = warpRedSum(v);
    if (lane == 0) sh[wid] = w;
    __syncthreads();
    if (wid == 0) {
        float t = (lane < 8) ? sh[lane] : 0.0f;
        t = warpRedSum(t);
        if (lane == 0) dst[row] = t;
    }
}
__global__ void zero_dsum_kernel() {
    if (threadIdx.x < Bb) g_dsum[threadIdx.x] = 0.0f;
}
__global__ void finalize_scale_kernel() {
    if (threadIdx.x < Bb)
        g_scale[threadIdx.x] =
            fmaxf(g_dsum[threadIdx.x] * (1.0f / ((float)Nn * (float)Mm)), 1e-4f);
}
__global__ void softmax_kernel(const float* __restrict__ ew_p) {
    const int row = blockIdx.x;
    const int b   = row / Nn;
    const float invsc = ew_p[0] / g_scale[b];
    const size_t base = (size_t)row * Mm;
    float v[8];
    float mx = -1e30f;
#pragma unroll
    for (int t = 0; t < 8; t++) {
        int idx = t * 256 + threadIdx.x;
        v[t] = g_L[base + idx] - g_D[base + idx] * invsc;
        mx = fmaxf(mx, v[t]);
    }
    __shared__ float sh[8];
    __shared__ float bc;
    int lane = threadIdx.x & 31, wid = threadIdx.x >> 5;
    float wm = warpRedMax(mx);
    if (lane == 0) sh[wid] = wm;
    __syncthreads();
    if (wid == 0) {
        float t = (lane < 8) ? sh[lane] : -1e30f;
        t = warpRedMax(t);
        if (lane == 0) bc = t;
    }
    __syncthreads();
    mx = bc;
    float sum = 0.0f;
#pragma unroll
    for (int t = 0; t < 8; t++) {
        v[t] = __expf(v[t] - mx);
        sum += v[t];
    }
    __syncthreads();
    float ws = warpRedSum(sum);
    if (lane == 0) sh[wid] = ws;
    __syncthreads();
    if (wid == 0) {
        float t = (lane < 8) ? sh[lane] : 0.0f;
        t = warpRedSum(t);
        if (lane == 0) bc = t;
    }
    __syncthreads();
    const float inv = 1.0f / bc;
#pragma unroll
    for (int t = 0; t < 8; t++) {
        int idx = t * 256 + threadIdx.x;
        g_L[base + idx] = v[t] * inv;
    }
}

// ---------------- launch ----------------
extern "C" void kernel_launch(void* const* d_in, const int* in_sizes, int n_in,
                              void* d_out, int out_size) {
    const float* q_fp  = (const float*)d_in[0];
    const float* v_ret = (const float*)d_in[1];
    const float* pi    = (const float*)d_in[2];
    const float* Wqs = (const float*)d_in[3];  const float* bqs = (const float*)d_in[4];
    const float* Wks = (const float*)d_in[5];  const float* bks = (const float*)d_in[6];
    const float* Wvs = (const float*)d_in[7];  const float* bvs = (const float*)d_in[8];
    const float* Wqe = (const float*)d_in[9];  const float* bqe = (const float*)d_in[10];
    const float* Wke = (const float*)d_in[11]; const float* bke = (const float*)d_in[12];
    const float* Wve = (const float*)d_in[13]; const float* bve = (const float*)d_in[14];
    const float* W1  = (const float*)d_in[15]; const float* b1  = (const float*)d_in[16];
    const float* W2  = (const float*)d_in[17]; const float* b2  = (const float*)d_in[18];
    const float* gamma = (const float*)d_in[19];
    const float* ew    = (const float*)d_in[20];
    float* out = (float*)d_out;

    float *qs_p, *qe_p, *ks_p, *vs_p, *ke_p, *ve_p, *q2_p, *k2_p, *fused_p, *h_p;
    cudaGetSymbolAddress((void**)&qs_p, g_qs);
    cudaGetSymbolAddress((void**)&qe_p, g_qe);
    cudaGetSymbolAddress((void**)&ks_p, g_ks);
    cudaGetSymbolAddress((void**)&vs_p, g_vs);
    cudaGetSymbolAddress((void**)&ke_p, g_ke);
    cudaGetSymbolAddress((void**)&ve_p, g_ve);
    cudaGetSymbolAddress((void**)&q2_p, g_q2);
    cudaGetSymbolAddress((void**)&k2_p, g_k2);
    cudaGetSymbolAddress((void**)&fused_p, g_fused);
    cudaGetSymbolAddress((void**)&h_p, g_hbuf);

    // projections: [16384,512] @ [512,256]
    dim3 gp(Hh / 128, (Bb * Nn) / 128);   // (2, 128)
    gemm3_kernel<<<gp, 256>>>(q_fp,  Wqs, bqs, qs_p, DIN, Hh, 0);
    gemm3_kernel<<<gp, 256>>>(q_fp,  Wqe, bqe, qe_p, DIN, Hh, 0);
    gemm3_kernel<<<gp, 256>>>(v_ret, Wks, bks, ks_p, DIN, Hh, 0);
    gemm3_kernel<<<gp, 256>>>(v_ret, Wvs, bvs, vs_p, DIN, Hh, 0);
    gemm3_kernel<<<gp, 256>>>(v_ret, Wke, bke, ke_p, DIN, Hh, 0);
    gemm3_kernel<<<gp, 256>>>(v_ret, Wve, bve, ve_p, DIN, Hh, 0);

    rowsumsq_kernel<<<Bb * Nn, 256>>>(qe_p, q2_p);
    rowsumsq_kernel<<<Bb * Mm, 256>>>(ke_p, k2_p);

    zero_dsum_kernel<<<1, 32>>>();
    dim3 gl(Mm / 64, Nn / 128, Bb);       // (32, 16, 8)
    logits3_kernel<<<gl, 256>>>(pi, gamma);
    finalize_scale_kernel<<<1, 32>>>();

    softmax_kernel<<<Bb * Nn, 256>>>(ew);

    dim3 gc(Hh / 64, Nn / 128, Bb);       // (4, 16, 8)
    ctx3_kernel<<<gc, 256>>>();

    dim3 gm(Hh / 128, (Bb * Nn) / 128);   // (2, 128)
    gemm3_kernel<<<gm, 256>>>(fused_p, W1, b1, h_p, 4 * Hh, Hh, 1);
    gemm3_kernel<<<gm, 256>>>(h_p,     W2, b2, out, Hh, Hh, 0);
}

// round 3
// speedup vs baseline: 2.2092x; 1.5586x over previous
#include <cuda_runtime.h>
#include <cstdint>

#define Bb 8
#define Nn 2048
#define Mm 2048
#define DIN 512
#define Hh 256

// ---------------- scratch (device globals; no allocs allowed) ----------------
__device__ float g_qs[(size_t)Bb*Nn*Hh];
__device__ float g_qe[(size_t)Bb*Nn*Hh];
__device__ float g_ks[(size_t)Bb*Mm*Hh];
__device__ float g_vs[(size_t)Bb*Mm*Hh];
__device__ float g_ke[(size_t)Bb*Mm*Hh];
__device__ float g_ve[(size_t)Bb*Mm*Hh];
__device__ float g_q2[Bb*Nn];
__device__ float g_k2[Bb*Mm];
__device__ float g_L[(size_t)Bb*Nn*Mm];   // logits, then probs in-place
__device__ float g_D[(size_t)Bb*Nn*Mm];   // electronic distance
__device__ float g_fused[(size_t)Bb*Nn*4*Hh];
__device__ float g_hbuf[(size_t)Bb*Nn*Hh];
__device__ float g_dsum[Bb];
__device__ float g_scale[Bb];

// ---------------- helpers ----------------
__device__ __forceinline__ uint32_t f2tf(float x) {
    uint32_t u;
    asm("cvt.rna.tf32.f32 %0, %1;" : "=r"(u) : "f"(x));
    return u;
}
__device__ __forceinline__ void split_tf32(float x, uint32_t& h, uint32_t& l) {
    h = f2tf(x);
    l = f2tf(x - __uint_as_float(h));
}
__device__ __forceinline__ void mma8(float* d, const uint32_t* a, uint32_t b0, uint32_t b1) {
    asm volatile(
        "mma.sync.aligned.m16n8k8.row.col.f32.tf32.tf32.f32 "
        "{%0,%1,%2,%3}, {%4,%5,%6,%7}, {%8,%9}, {%0,%1,%2,%3};\n"
        : "+f"(d[0]), "+f"(d[1]), "+f"(d[2]), "+f"(d[3])
        : "r"(a[0]), "r"(a[1]), "r"(a[2]), "r"(a[3]), "r"(b0), "r"(b1));
}
__device__ __forceinline__ void cpa16(void* smem, const void* gmem) {
    uint32_t s = (uint32_t)__cvta_generic_to_shared(smem);
    asm volatile("cp.async.cg.shared.global [%0], [%1], 16;\n" :: "r"(s), "l"(gmem));
}
#define CP_COMMIT() asm volatile("cp.async.commit_group;\n")
#define CP_WAIT1()  asm volatile("cp.async.wait_group 1;\n")
#define CP_WAIT0()  asm volatile("cp.async.wait_group 0;\n")

__device__ __forceinline__ float warpRedSum(float v) {
#pragma unroll
    for (int o = 16; o > 0; o >>= 1) v += __shfl_xor_sync(0xffffffffu, v, o);
    return v;
}
__device__ __forceinline__ float warpRedMax(float v) {
#pragma unroll
    for (int o = 16; o > 0; o >>= 1) v = fmaxf(v, __shfl_xor_sync(0xffffffffu, v, o));
    return v;
}

// =============================================================================
// Generic 3xTF32 GEMM: C[R,Nc] = A[R,K] @ W[K,Nc] + bias, optional SiLU.
// 128x128 tile, BK=16, 2-stage cp.async pipeline, 8 warps (4x2), warp 32x64.
// =============================================================================
__global__ __launch_bounds__(256, 2) void gemm3_kernel(
    const float* __restrict__ A, const float* __restrict__ W,
    const float* __restrict__ bias, float* __restrict__ C,
    int K, int Nc, int act)
{
    __shared__ float As[2][128][20];   // [m][k] pad 20 -> conflict-free frags
    __shared__ float Bs[2][16][136];   // [k][n] pad 136 -> conflict-free frags
    const int row0 = blockIdx.y * 128;
    const int col0 = blockIdx.x * 128;
    const int tid  = threadIdx.x;
    const int lane = tid & 31, warp = tid >> 5;
    const int wR = warp >> 1, wC = warp & 1;

    float acc[2][8][4] = {};

    const int nk = K / 16;
    {   // prologue: stage 0
#pragma unroll
        for (int it = 0; it < 2; it++) {
            int i = tid + it * 256;
            int r = i >> 2, c4 = (i & 3) * 4;
            cpa16(&As[0][r][c4], &A[(size_t)(row0 + r) * K + c4]);
        }
#pragma unroll
        for (int it = 0; it < 2; it++) {
            int i = tid + it * 256;
            int r = i >> 5, c4 = (i & 31) * 4;
            cpa16(&Bs[0][r][c4], &W[(size_t)r * Nc + col0 + c4]);
        }
        CP_COMMIT();
    }

    for (int kt = 0; kt < nk; kt++) {
        const int s = kt & 1;
        if (kt + 1 < nk) {
            const int k0 = (kt + 1) * 16;
            const int sn = s ^ 1;
#pragma unroll
            for (int it = 0; it < 2; it++) {
                int i = tid + it * 256;
                int r = i >> 2, c4 = (i & 3) * 4;
                cpa16(&As[sn][r][c4], &A[(size_t)(row0 + r) * K + k0 + c4]);
            }
#pragma unroll
            for (int it = 0; it < 2; it++) {
                int i = tid + it * 256;
                int r = i >> 5, c4 = (i & 31) * 4;
                cpa16(&Bs[sn][r][c4], &W[(size_t)(k0 + r) * Nc + col0 + c4]);
            }
            CP_COMMIT();
            CP_WAIT1();
        } else {
            CP_WAIT0();
        }
        __syncthreads();
#pragma unroll
        for (int ks = 0; ks < 2; ks++) {
            const int kb = ks * 8;
            const int kk = kb + (lane & 3);
            uint32_t aH[2][4], aL[2][4];
#pragma unroll
            for (int i = 0; i < 2; i++) {
                int m = wR * 32 + i * 16 + (lane >> 2);
                split_tf32(As[s][m][kk],         aH[i][0], aL[i][0]);
                split_tf32(As[s][m + 8][kk],     aH[i][1], aL[i][1]);
                split_tf32(As[s][m][kk + 4],     aH[i][2], aL[i][2]);
                split_tf32(As[s][m + 8][kk + 4], aH[i][3], aL[i][3]);
            }
#pragma unroll
            for (int j = 0; j < 8; j++) {
                int n = wC * 64 + j * 8 + (lane >> 2);
                uint32_t bh0, bl0, bh1, bl1;
                split_tf32(Bs[s][kb + (lane & 3)][n],     bh0, bl0);
                split_tf32(Bs[s][kb + 4 + (lane & 3)][n], bh1, bl1);
#pragma unroll
                for (int i = 0; i < 2; i++) {
                    mma8(acc[i][j], aH[i], bh0, bh1);
                    mma8(acc[i][j], aH[i], bl0, bl1);
                    mma8(acc[i][j], aL[i], bh0, bh1);
                }
            }
        }
        __syncthreads();
    }
#pragma unroll
    for (int i = 0; i < 2; i++) {
        int r = row0 + wR * 32 + i * 16 + (lane >> 2);
#pragma unroll
        for (int j = 0; j < 8; j++) {
            int c = col0 + wC * 64 + j * 8 + 2 * (lane & 3);
            float b0 = bias[c], b1 = bias[c + 1];
            float v0 = acc[i][j][0] + b0, v1 = acc[i][j][1] + b1;
            float v2 = acc[i][j][2] + b0, v3 = acc[i][j][3] + b1;
            if (act) {
                v0 = v0 / (1.0f + __expf(-v0));
                v1 = v1 / (1.0f + __expf(-v1));
                v2 = v2 / (1.0f + __expf(-v2));
                v3 = v3 / (1.0f + __expf(-v3));
            }
            *(float2*)&C[(size_t)r * Nc + c]       = make_float2(v0, v1);
            *(float2*)&C[(size_t)(r + 8) * Nc + c] = make_float2(v2, v3);
        }
    }
}

// =============================================================================
// Logits: dual 3xTF32 NT GEMM + dist/pi epilogue + dist-sum.
// Block 128(n) x 64(m), BK=32, 2-stage cp.async, dynamic smem (110.6 KB).
// =============================================================================
#define QS(s,r,c) QsP[((s)*128 + (r)) * 36 + (c)]
#define QE(s,r,c) QeP[((s)*128 + (r)) * 36 + (c)]
#define KS(s,r,c) KsP[((s)*64  + (r)) * 36 + (c)]
#define KE(s,r,c) KeP[((s)*64  + (r)) * 36 + (c)]

__global__ __launch_bounds__(256) void logits3_kernel(
    const float* __restrict__ pi_star, const float* __restrict__ gamma_p)
{
    extern __shared__ float sm[];
    float* QsP = sm;                       // 2*128*36
    float* QeP = QsP + 2 * 128 * 36;
    float* KsP = QeP + 2 * 128 * 36;       // 2*64*36
    float* KeP = KsP + 2 * 64 * 36;

    const int b  = blockIdx.z;
    const int n0 = blockIdx.y * 128;
    const int m0 = blockIdx.x * 64;
    const int tid = threadIdx.x;
    const int lane = tid & 31, warp = tid >> 5;
    const int wR = warp >> 1, wC = warp & 1;

    const float* qs = g_qs + (size_t)(b * Nn + n0) * Hh;
    const float* qe = g_qe + (size_t)(b * Nn + n0) * Hh;
    const float* ks = g_ks + (size_t)(b * Mm + m0) * Hh;
    const float* ke = g_ke + (size_t)(b * Mm + m0) * Hh;

    float accS[2][4][4] = {}, accE[2][4][4] = {};

    const int nk = Hh / 32;   // 8
    {   // prologue
#pragma unroll
        for (int it = 0; it < 4; it++) {
            int i = tid + it * 256;
            int r = i >> 3, c4 = (i & 7) * 4;
            cpa16(&QS(0, r, c4), qs + (size_t)r * Hh + c4);
            cpa16(&QE(0, r, c4), qe + (size_t)r * Hh + c4);
        }
#pragma unroll
        for (int it = 0; it < 2; it++) {
            int i = tid + it * 256;
            int r = i >> 3, c4 = (i & 7) * 4;
            cpa16(&KS(0, r, c4), ks + (size_t)r * Hh + c4);
            cpa16(&KE(0, r, c4), ke + (size_t)r * Hh + c4);
        }
        CP_COMMIT();
    }

    for (int kt = 0; kt < nk; kt++) {
        const int s = kt & 1;
        if (kt + 1 < nk) {
            const int k0 = (kt + 1) * 32;
            const int sn = s ^ 1;
#pragma unroll
            for (int it = 0; it < 4; it++) {
                int i = tid + it * 256;
                int r = i >> 3, c4 = (i & 7) * 4;
                cpa16(&QS(sn, r, c4), qs + (size_t)r * Hh + k0 + c4);
                cpa16(&QE(sn, r, c4), qe + (size_t)r * Hh + k0 + c4);
            }
#pragma unroll
            for (int it = 0; it < 2; it++) {
                int i = tid + it * 256;
                int r = i >> 3, c4 = (i & 7) * 4;
                cpa16(&KS(sn, r, c4), ks + (size_t)r * Hh + k0 + c4);
                cpa16(&KE(sn, r, c4), ke + (size_t)r * Hh + k0 + c4);
            }
            CP_COMMIT();
            CP_WAIT1();
        } else {
            CP_WAIT0();
        }
        __syncthreads();
#pragma unroll
        for (int ksl = 0; ksl < 4; ksl++) {
            const int kb = ksl * 8;
            const int kk = kb + (lane & 3);
            uint32_t asH[2][4], asL[2][4], aeH[2][4], aeL[2][4];
#pragma unroll
            for (int i = 0; i < 2; i++) {
                int m = wR * 32 + i * 16 + (lane >> 2);
                split_tf32(QS(s, m, kk),         asH[i][0], asL[i][0]);
                split_tf32(QS(s, m + 8, kk),     asH[i][1], asL[i][1]);
                split_tf32(QS(s, m, kk + 4),     asH[i][2], asL[i][2]);
                split_tf32(QS(s, m + 8, kk + 4), asH[i][3], asL[i][3]);
                split_tf32(QE(s, m, kk),         aeH[i][0], aeL[i][0]);
                split_tf32(QE(s, m + 8, kk),     aeH[i][1], aeL[i][1]);
                split_tf32(QE(s, m, kk + 4),     aeH[i][2], aeL[i][2]);
                split_tf32(QE(s, m + 8, kk + 4), aeH[i][3], aeL[i][3]);
            }
#pragma unroll
            for (int j = 0; j < 4; j++) {
                int n = wC * 32 + j * 8 + (lane >> 2);
                uint32_t bsh0, bsl0, bsh1, bsl1, beh0, bel0, beh1, bel1;
                split_tf32(KS(s, n, kk),     bsh0, bsl0);
                split_tf32(KS(s, n, kk + 4), bsh1, bsl1);
                split_tf32(KE(s, n, kk),     beh0, bel0);
                split_tf32(KE(s, n, kk + 4), beh1, bel1);
#pragma unroll
                for (int i = 0; i < 2; i++) {
                    mma8(accS[i][j], asH[i], bsh0, bsh1);
                    mma8(accS[i][j], asH[i], bsl0, bsl1);
                    mma8(accS[i][j], asL[i], bsh0, bsh1);
                    mma8(accE[i][j], aeH[i], beh0, beh1);
                    mma8(accE[i][j], aeH[i], bel0, bel1);
                    mma8(accE[i][j], aeL[i], beh0, beh1);
                }
            }
        }
        __syncthreads();
    }

    const float g = gamma_p[0];
    float sumd = 0.0f;
#pragma unroll
    for (int i = 0; i < 2; i++) {
        int n_lo = n0 + wR * 32 + i * 16 + (lane >> 2);
        float q2a = g_q2[b * Nn + n_lo];
        float q2b = g_q2[b * Nn + n_lo + 8];
#pragma unroll
        for (int j = 0; j < 4; j++) {
            int m = m0 + wC * 32 + j * 8 + 2 * (lane & 3);
            float k2a = g_k2[b * Mm + m], k2b = g_k2[b * Mm + m + 1];
            size_t base0 = ((size_t)b * Nn + n_lo) * Mm + m;
            float2 piv = *(const float2*)&pi_star[base0];
            float d0 = sqrtf(fmaxf(q2a + k2a - 2.0f * accE[i][j][0], 1e-12f));
            float d1 = sqrtf(fmaxf(q2a + k2b - 2.0f * accE[i][j][1], 1e-12f));
            sumd += d0 + d1;
            *(float2*)&g_D[base0] = make_float2(d0, d1);
            float L0 = accS[i][j][0] * 0.0625f + g * __logf(fmaxf(piv.x, 1e-9f));
            float L1 = accS[i][j][1] * 0.0625f + g * __logf(fmaxf(piv.y, 1e-9f));
            *(float2*)&g_L[base0] = make_float2(L0, L1);
            size_t base1 = ((size_t)b * Nn + n_lo + 8) * Mm + m;
            piv = *(const float2*)&pi_star[base1];
            float d2v = sqrtf(fmaxf(q2b + k2a - 2.0f * accE[i][j][2], 1e-12f));
            float d3v = sqrtf(fmaxf(q2b + k2b - 2.0f * accE[i][j][3], 1e-12f));
            sumd += d2v + d3v;
            *(float2*)&g_D[base1] = make_float2(d2v, d3v);
            float L2 = accS[i][j][2] * 0.0625f + g * __logf(fmaxf(piv.x, 1e-9f));
            float L3 = accS[i][j][3] * 0.0625f + g * __logf(fmaxf(piv.y, 1e-9f));
            *(float2*)&g_L[base1] = make_float2(L2, L3);
        }
    }
    // block reduce dist-sum (reuse smem; all compute done, loop ended with sync)
    sm[tid] = sumd;
    __syncthreads();
    for (int sred = 128; sred > 0; sred >>= 1) {
        if (tid < sred) sm[tid] += sm[tid + sred];
        __syncthreads();
    }
    if (tid == 0) atomicAdd(&g_dsum[b], sm[0]);
}

// =============================================================================
// Ctx: dual 3xTF32 NN GEMM attn@Vs / attn@Ve -> fused features.
// Block 128(n) x 64(h), BK=32, 2-stage cp.async, dynamic smem (73.7 KB).
// =============================================================================
#define PS_(s,r,c) PsP[((s)*128 + (r)) * 36 + (c)]
#define VS_(s,r,c) VsP[((s)*32  + (r)) * 72 + (c)]
#define VE_(s,r,c) VeP[((s)*32  + (r)) * 72 + (c)]

__global__ __launch_bounds__(256) void ctx3_kernel()
{
    extern __shared__ float sm[];
    float* PsP = sm;                       // 2*128*36
    float* VsP = PsP + 2 * 128 * 36;       // 2*32*72
    float* VeP = VsP + 2 * 32 * 72;

    const int b  = blockIdx.z;
    const int n0 = blockIdx.y * 128;
    const int h0 = blockIdx.x * 64;
    const int tid = threadIdx.x;
    const int lane = tid & 31, warp = tid >> 5;
    const int wR = warp >> 1, wC = warp & 1;

    float accS[2][4][4] = {}, accE[2][4][4] = {};

    const int nk = Mm / 32;  // 64
    {   // prologue
#pragma unroll
        for (int it = 0; it < 4; it++) {
            int i = tid + it * 256;
            int r = i >> 3, c4 = (i & 7) * 4;
            cpa16(&PS_(0, r, c4), &g_L[((size_t)b * Nn + n0 + r) * Mm + c4]);
        }
#pragma unroll
        for (int it = 0; it < 2; it++) {
            int i = tid + it * 256;
            int r = i >> 4, c4 = (i & 15) * 4;
            size_t off = ((size_t)b * Mm + r) * Hh + h0 + c4;
            cpa16(&VS_(0, r, c4), &g_vs[off]);
            cpa16(&VE_(0, r, c4), &g_ve[off]);
        }
        CP_COMMIT();
    }

    for (int kt = 0; kt < nk; kt++) {
        const int s = kt & 1;
        if (kt + 1 < nk) {
            const int m0n = (kt + 1) * 32;
            const int sn = s ^ 1;
#pragma unroll
            for (int it = 0; it < 4; it++) {
                int i = tid + it * 256;
                int r = i >> 3, c4 = (i & 7) * 4;
                cpa16(&PS_(sn, r, c4), &g_L[((size_t)b * Nn + n0 + r) * Mm + m0n + c4]);
            }
#pragma unroll
            for (int it = 0; it < 2; it++) {
                int i = tid + it * 256;
                int r = i >> 4, c4 = (i & 15) * 4;
                size_t off = ((size_t)b * Mm + m0n + r) * Hh + h0 + c4;
                cpa16(&VS_(sn, r, c4), &g_vs[off]);
                cpa16(&VE_(sn, r, c4), &g_ve[off]);
            }
            CP_COMMIT();
            CP_WAIT1();
        } else {
            CP_WAIT0();
        }
        __syncthreads();
#pragma unroll
        for (int ksl = 0; ksl < 4; ksl++) {
            const int kb = ksl * 8;
            const int kk = kb + (lane & 3);
            uint32_t aH[2][4], aL[2][4];
#pragma unroll
            for (int i = 0; i < 2; i++) {
                int m = wR * 32 + i * 16 + (lane >> 2);
                split_tf32(PS_(s, m, kk),         aH[i][0], aL[i][0]);
                split_tf32(PS_(s, m + 8, kk),     aH[i][1], aL[i][1]);
                split_tf32(PS_(s, m, kk + 4),     aH[i][2], aL[i][2]);
                split_tf32(PS_(s, m + 8, kk + 4), aH[i][3], aL[i][3]);
            }
#pragma unroll
            for (int j = 0; j < 4; j++) {
                int n = wC * 32 + j * 8 + (lane >> 2);
                uint32_t sh0, sl0, sh1, sl1, eh0, el0, eh1, el1;
                split_tf32(VS_(s, kb + (lane & 3), n),     sh0, sl0);
                split_tf32(VS_(s, kb + 4 + (lane & 3), n), sh1, sl1);
                split_tf32(VE_(s, kb + (lane & 3), n),     eh0, el0);
                split_tf32(VE_(s, kb + 4 + (lane & 3), n), eh1, el1);
#pragma unroll
                for (int i = 0; i < 2; i++) {
                    mma8(accS[i][j], aH[i], sh0, sh1);
                    mma8(accS[i][j], aH[i], sl0, sl1);
                    mma8(accS[i][j], aL[i], sh0, sh1);
                    mma8(accE[i][j], aH[i], eh0, eh1);
                    mma8(accE[i][j], aH[i], el0, el1);
                    mma8(accE[i][j], aL[i], eh0, eh1);
                }
            }
        }
        __syncthreads();
    }
#pragma unroll
    for (int i = 0; i < 2; i++) {
        int n_lo = n0 + wR * 32 + i * 16 + (lane >> 2);
#pragma unroll
        for (int j = 0; j < 4; j++) {
            int h = h0 + wC * 32 + j * 8 + 2 * (lane & 3);
#pragma unroll
            for (int half = 0; half < 2; half++) {
                int n = n_lo + half * 8;
                float cs0 = accS[i][j][half * 2 + 0], cs1 = accS[i][j][half * 2 + 1];
                float ce0 = accE[i][j][half * 2 + 0], ce1 = accE[i][j][half * 2 + 1];
                size_t fb = ((size_t)b * Nn + n) * (4 * Hh);
                *(float2*)&g_fused[fb + h]          = make_float2(cs0, cs1);
                *(float2*)&g_fused[fb + Hh + h]     = make_float2(ce0, ce1);
                *(float2*)&g_fused[fb + 2 * Hh + h] = make_float2(cs0 - ce0, cs1 - ce1);
                *(float2*)&g_fused[fb + 3 * Hh + h] = make_float2(cs0 * ce0, cs1 * ce1);
            }
        }
    }
}

// ---------------- small kernels ----------------
__global__ void rowsumsq_kernel(const float* __restrict__ src, float* __restrict__ dst) {
    const int row = blockIdx.x;
    float v = src[(size_t)row * Hh + threadIdx.x];
    v *= v;
    __shared__ float sh[8];
    int lane = threadIdx.x & 31, wid = threadIdx.x >> 5;
    float w = warpRedSum(v);
    if (lane == 0) sh[wid] = w;
    __syncthreads();
    if (wid == 0) {
        float t = (lane < 8) ? sh[lane] : 0.0f;
        t = warpRedSum(t);
        if (lane == 0) dst[row] = t;
    }
}
__global__ void zero_dsum_kernel() {
    if (threadIdx.x < Bb) g_dsum[threadIdx.x] = 0.0f;
}
__global__ void finalize_scale_kernel() {
    if (threadIdx.x < Bb)
        g_scale[threadIdx.x] =
            fmaxf(g_dsum[threadIdx.x] * (1.0f / ((float)Nn * (float)Mm)), 1e-4f);
}
__global__ void softmax_kernel(const float* __restrict__ ew_p) {
    const int row = blockIdx.x;
    const int b   = row / Nn;
    const float invsc = ew_p[0] / g_scale[b];
    const size_t base = (size_t)row * Mm;
    float v[8];
    float mx = -1e30f;
#pragma unroll
    for (int t = 0; t < 8; t++) {
        int idx = t * 256 + threadIdx.x;
        v[t] = g_L[base + idx] - g_D[base + idx] * invsc;
        mx = fmaxf(mx, v[t]);
    }
    __shared__ float sh[8];
    __shared__ float bc;
    int lane = threadIdx.x & 31, wid = threadIdx.x >> 5;
    float wm = warpRedMax(mx);
    if (lane == 0) sh[wid] = wm;
    __syncthreads();
    if (wid == 0) {
        float t = (lane < 8) ? sh[lane] : -1e30f;
        t = warpRedMax(t);
        if (lane == 0) bc = t;
    }
    __syncthreads();
    mx = bc;
    float sum = 0.0f;
#pragma unroll
    for (int t = 0; t < 8; t++) {
        v[t] = __expf(v[t] - mx);
        sum += v[t];
    }
    __syncthreads();
    float ws = warpRedSum(sum);
    if (lane == 0) sh[wid] = ws;
    __syncthreads();
    if (wid == 0) {
        float t = (lane < 8) ? sh[lane] : 0.0f;
        t = warpRedSum(t);
        if (lane == 0) bc = t;
    }
    __syncthreads();
    const float inv = 1.0f / bc;
#pragma unroll
    for (int t = 0; t < 8; t++) {
        int idx = t * 256 + threadIdx.x;
        g_L[base + idx] = v[t] * inv;
    }
}

// ---------------- launch ----------------
extern "C" void kernel_launch(void* const* d_in, const int* in_sizes, int n_in,
                              void* d_out, int out_size) {
    const float* q_fp  = (const float*)d_in[0];
    const float* v_ret = (const float*)d_in[1];
    const float* pi    = (const float*)d_in[2];
    const float* Wqs = (const float*)d_in[3];  const float* bqs = (const float*)d_in[4];
    const float* Wks = (const float*)d_in[5];  const float* bks = (const float*)d_in[6];
    const float* Wvs = (const float*)d_in[7];  const float* bvs = (const float*)d_in[8];
    const float* Wqe = (const float*)d_in[9];  const float* bqe = (const float*)d_in[10];
    const float* Wke = (const float*)d_in[11]; const float* bke = (const float*)d_in[12];
    const float* Wve = (const float*)d_in[13]; const float* bve = (const float*)d_in[14];
    const float* W1  = (const float*)d_in[15]; const float* b1  = (const float*)d_in[16];
    const float* W2  = (const float*)d_in[17]; const float* b2  = (const float*)d_in[18];
    const float* gamma = (const float*)d_in[19];
    const float* ew    = (const float*)d_in[20];
    float* out = (float*)d_out;

    float *qs_p, *qe_p, *ks_p, *vs_p, *ke_p, *ve_p, *q2_p, *k2_p, *fused_p, *h_p;
    cudaGetSymbolAddress((void**)&qs_p, g_qs);
    cudaGetSymbolAddress((void**)&qe_p, g_qe);
    cudaGetSymbolAddress((void**)&ks_p, g_ks);
    cudaGetSymbolAddress((void**)&vs_p, g_vs);
    cudaGetSymbolAddress((void**)&ke_p, g_ke);
    cudaGetSymbolAddress((void**)&ve_p, g_ve);
    cudaGetSymbolAddress((void**)&q2_p, g_q2);
    cudaGetSymbolAddress((void**)&k2_p, g_k2);
    cudaGetSymbolAddress((void**)&fused_p, g_fused);
    cudaGetSymbolAddress((void**)&h_p, g_hbuf);

    const int LOGITS_SMEM = (2*128*36*2 + 2*64*36*2) * 4;   // 110592 B
    const int CTX_SMEM    = (2*128*36 + 2*32*72*2) * 4;     //  73728 B
    cudaFuncSetAttribute(logits3_kernel, cudaFuncAttributeMaxDynamicSharedMemorySize, LOGITS_SMEM);
    cudaFuncSetAttribute(ctx3_kernel,    cudaFuncAttributeMaxDynamicSharedMemorySize, CTX_SMEM);

    // projections: [16384,512] @ [512,256]
    dim3 gp(Hh / 128, (Bb * Nn) / 128);   // (2, 128)
    gemm3_kernel<<<gp, 256>>>(q_fp,  Wqs, bqs, qs_p, DIN, Hh, 0);
    gemm3_kernel<<<gp, 256>>>(q_fp,  Wqe, bqe, qe_p, DIN, Hh, 0);
    gemm3_kernel<<<gp, 256>>>(v_ret, Wks, bks, ks_p, DIN, Hh, 0);
    gemm3_kernel<<<gp, 256>>>(v_ret, Wvs, bvs, vs_p, DIN, Hh, 0);
    gemm3_kernel<<<gp, 256>>>(v_ret, Wke, bke, ke_p, DIN, Hh, 0);
    gemm3_kernel<<<gp, 256>>>(v_ret, Wve, bve, ve_p, DIN, Hh, 0);

    rowsumsq_kernel<<<Bb * Nn, 256>>>(qe_p, q2_p);
    rowsumsq_kernel<<<Bb * Mm, 256>>>(ke_p, k2_p);

    zero_dsum_kernel<<<1, 32>>>();
    dim3 gl(Mm / 64, Nn / 128, Bb);       // (32, 16, 8)
    logits3_kernel<<<gl, 256, LOGITS_SMEM>>>(pi, gamma);
    finalize_scale_kernel<<<1, 32>>>();

    softmax_kernel<<<Bb * Nn, 256>>>(ew);

    dim3 gc(Hh / 64, Nn / 128, Bb);       // (4, 16, 8)
    ctx3_kernel<<<gc, 256, CTX_SMEM>>>();

    dim3 gm(Hh / 128, (Bb * Nn) / 128);   // (2, 128)
    gemm3_kernel<<<gm, 256>>>(fused_p, W1, b1, h_p, 4 * Hh, Hh, 1);
    gemm3_kernel<<<gm, 256>>>(h_p,     W2, b2, out, Hh, Hh, 0);
}

// round 4
// speedup vs baseline: 3.6508x; 1.6525x over previous
#include <cuda_runtime.h>
#include <cuda_bf16.h>
#include <cstdint>

#define Bb 8
#define Nn 2048
#define Mm 2048
#define DIN 512
#define Hh 256

// ---------------- scratch (device globals; no allocs allowed) ----------------
// packed bf16 hi/lo planes: u32 = (bf16 even | bf16 odd << 16) along k
__device__ uint32_t g_qfH[(size_t)Bb*Nn*DIN/2], g_qfL[(size_t)Bb*Nn*DIN/2];
__device__ uint32_t g_vrH[(size_t)Bb*Mm*DIN/2], g_vrL[(size_t)Bb*Mm*DIN/2];
// packed weights: Wqs..Wve (6 x 256x256), W1 (512x256), W2 (128x256)
__device__ uint32_t g_wH[6*65536 + 131072 + 32768], g_wL[6*65536 + 131072 + 32768];
// projections packed (pairs along h): [B*N][128]
__device__ uint32_t g_qsH[(size_t)Bb*Nn*128], g_qsL[(size_t)Bb*Nn*128];
__device__ uint32_t g_qeH[(size_t)Bb*Nn*128], g_qeL[(size_t)Bb*Nn*128];
__device__ uint32_t g_ksH[(size_t)Bb*Mm*128], g_ksL[(size_t)Bb*Mm*128];
__device__ uint32_t g_keH[(size_t)Bb*Mm*128], g_keL[(size_t)Bb*Mm*128];
// V fp32 then transposed-packed: [B][H][M/2]
__device__ float    g_vs[(size_t)Bb*Mm*Hh], g_ve[(size_t)Bb*Mm*Hh];
__device__ uint32_t g_vsTH[(size_t)Bb*Hh*1024], g_vsTL[(size_t)Bb*Hh*1024];
__device__ uint32_t g_veTH[(size_t)Bb*Hh*1024], g_veTL[(size_t)Bb*Hh*1024];
// logits / dist fp32, probs packed
__device__ float    g_L[(size_t)Bb*Nn*Mm];
__device__ float    g_D[(size_t)Bb*Nn*Mm];
__device__ uint32_t g_pH[(size_t)Bb*Nn*1024], g_pL[(size_t)Bb*Nn*1024];
// fused / hidden packed
__device__ uint32_t g_fH[(size_t)Bb*Nn*512], g_fL[(size_t)Bb*Nn*512];
__device__ uint32_t g_hH[(size_t)Bb*Nn*128], g_hL[(size_t)Bb*Nn*128];
__device__ float g_q2[Bb*Nn], g_k2[Bb*Mm], g_dsum[Bb], g_scale[Bb];

// ---------------- helpers ----------------
__device__ __forceinline__ void split2(float f0, float f1, uint32_t& H, uint32_t& L) {
    __nv_bfloat16 h0 = __float2bfloat16(f0);
    __nv_bfloat16 h1 = __float2bfloat16(f1);
    __nv_bfloat16 l0 = __float2bfloat16(f0 - __bfloat162float(h0));
    __nv_bfloat16 l1 = __float2bfloat16(f1 - __bfloat162float(h1));
    H = (uint32_t)__bfloat16_as_ushort(h0) | ((uint32_t)__bfloat16_as_ushort(h1) << 16);
    L = (uint32_t)__bfloat16_as_ushort(l0) | ((uint32_t)__bfloat16_as_ushort(l1) << 16);
}
__device__ __forceinline__ float bflo(uint32_t u) {
    return __bfloat162float(__ushort_as_bfloat16((unsigned short)(u & 0xffff)));
}
__device__ __forceinline__ float bfhi(uint32_t u) {
    return __bfloat162float(__ushort_as_bfloat16((unsigned short)(u >> 16)));
}
__device__ __forceinline__ void mmabf(float* d, const uint32_t* a, uint32_t b0, uint32_t b1) {
    asm volatile(
        "mma.sync.aligned.m16n8k16.row.col.f32.bf16.bf16.f32 "
        "{%0,%1,%2,%3}, {%4,%5,%6,%7}, {%8,%9}, {%0,%1,%2,%3};\n"
        : "+f"(d[0]), "+f"(d[1]), "+f"(d[2]), "+f"(d[3])
        : "r"(a[0]), "r"(a[1]), "r"(a[2]), "r"(a[3]), "r"(b0), "r"(b1));
}
__device__ __forceinline__ void cpa16(void* smem, const void* gmem) {
    uint32_t s = (uint32_t)__cvta_generic_to_shared(smem);
    asm volatile("cp.async.cg.shared.global [%0], [%1], 16;\n" :: "r"(s), "l"(gmem));
}
#define CP_COMMIT() asm volatile("cp.async.commit_group;\n")
#define CP_WAIT1()  asm volatile("cp.async.wait_group 1;\n")
#define CP_WAIT0()  asm volatile("cp.async.wait_group 0;\n")

__device__ __forceinline__ float warpRedSum(float v) {
#pragma unroll
    for (int o = 16; o > 0; o >>= 1) v += __shfl_xor_sync(0xffffffffu, v, o);
    return v;
}
__device__ __forceinline__ float warpRedMax(float v) {
#pragma unroll
    for (int o = 16; o > 0; o >>= 1) v = fmaxf(v, __shfl_xor_sync(0xffffffffu, v, o));
    return v;
}

// ---------------- prep kernels ----------------
__global__ void pack_rows_kernel(const float* __restrict__ src,
                                 uint32_t* __restrict__ H, uint32_t* __restrict__ L,
                                 int npairs) {
    int i = blockIdx.x * 256 + threadIdx.x;
    if (i >= npairs) return;
    float2 f = ((const float2*)src)[i];
    uint32_t h, l; split2(f.x, f.y, h, l);
    H[i] = h; L[i] = l;
}
__global__ void pack_weight_kernel(const float* __restrict__ W,
                                   uint32_t* __restrict__ H, uint32_t* __restrict__ L,
                                   int Kp, int Nc) {
    int i = blockIdx.x * 256 + threadIdx.x;
    if (i >= Kp * Nc) return;
    int kp = i / Nc, n = i - kp * Nc;
    float f0 = W[(size_t)(2 * kp) * Nc + n];
    float f1 = W[(size_t)(2 * kp + 1) * Nc + n];
    uint32_t h, l; split2(f0, f1, h, l);
    H[i] = h; L[i] = l;
}
// V [b][m][h] fp32 -> VT packed [b][h][m/2]
__global__ void transpose_pack_kernel(const float* __restrict__ V,
                                      uint32_t* __restrict__ H, uint32_t* __restrict__ L) {
    __shared__ float t[64][33];
    const int b = blockIdx.z, m0 = blockIdx.x * 64, h0 = blockIdx.y * 32;
    const int tid = threadIdx.x;
#pragma unroll
    for (int it = 0; it < 2; it++) {
        int i = tid + it * 256;
        int m = i >> 3, h4 = (i & 7) * 4;
        float4 v = *(const float4*)&V[((size_t)b * Mm + m0 + m) * Hh + h0 + h4];
        t[m][h4 + 0] = v.x; t[m][h4 + 1] = v.y; t[m][h4 + 2] = v.z; t[m][h4 + 3] = v.w;
    }
    __syncthreads();
#pragma unroll
    for (int u = 0; u < 4; u++) {
        int i = tid + u * 256;
        int h = i >> 5, mp = i & 31;
        float f0 = t[2 * mp][h], f1 = t[2 * mp + 1][h];
        uint32_t hh, ll; split2(f0, f1, hh, ll);
        size_t o = ((size_t)b * Hh + h0 + h) * 1024 + (m0 >> 1) + mp;
        H[o] = hh; L[o] = ll;
    }
}
// row sum of squares from packed (row length 128 u32 = 256 elems), block 128
__global__ void rowsumsq_kernel(const uint32_t* __restrict__ H, const uint32_t* __restrict__ L,
                                float* __restrict__ dst) {
    const int row = blockIdx.x, tid = threadIdx.x;
    uint32_t h = H[(size_t)row * 128 + tid], l = L[(size_t)row * 128 + tid];
    float v0 = bflo(h) + bflo(l), v1 = bfhi(h) + bfhi(l);
    float s = v0 * v0 + v1 * v1;
    __shared__ float sh[4];
    int lane = tid & 31, wid = tid >> 5;
    float w = warpRedSum(s);
    if (lane == 0) sh[wid] = w;
    __syncthreads();
    if (wid == 0) {
        float t = (lane < 4) ? sh[lane] : 0.0f;
        t = warpRedSum(t);
        if (lane == 0) dst[row] = t;
    }
}
__global__ void zero_dsum_kernel() { if (threadIdx.x < Bb) g_dsum[threadIdx.x] = 0.0f; }
__global__ void finalize_scale_kernel() {
    if (threadIdx.x < Bb)
        g_scale[threadIdx.x] = fmaxf(g_dsum[threadIdx.x] * (1.0f / ((float)Nn * (float)Mm)), 1e-4f);
}

// =============================================================================
// Packed bf16x3 GEMM: C[R,Nc] = A[R,K] @ W[K,Nc] + bias (+SiLU) (+packed out)
// tile 128x128, BK=32 fp32 (16 pairs), 2-stage cp.async, 8 warps, warp 32x64.
// =============================================================================
#define AHs(s,r,c) smA_H[((s)*128 + (r))*20 + (c)]
#define ALs(s,r,c) smA_L[((s)*128 + (r))*20 + (c)]
#define BHs(s,r,c) smB_H[((s)*16  + (r))*136 + (c)]
#define BLs(s,r,c) smB_L[((s)*16  + (r))*136 + (c)]

__global__ __launch_bounds__(256, 2) void gemmP_kernel(
    const uint32_t* __restrict__ aH, const uint32_t* __restrict__ aL,
    const uint32_t* __restrict__ wH, const uint32_t* __restrict__ wL,
    const float* __restrict__ bias,
    float* __restrict__ outF, uint32_t* __restrict__ outH, uint32_t* __restrict__ outL,
    int Kp, int Nc, int act, int packedOut)
{
    extern __shared__ uint32_t smu[];
    uint32_t* smA_H = smu;                 // 2*128*20 = 5120
    uint32_t* smA_L = smA_H + 5120;
    uint32_t* smB_H = smA_L + 5120;        // 2*16*136 = 4352
    uint32_t* smB_L = smB_H + 4352;

    const int row0 = blockIdx.y * 128;
    const int col0 = blockIdx.x * 128;
    const int tid  = threadIdx.x;
    const int lane = tid & 31, warp = tid >> 5;
    const int wR = warp >> 1, wC = warp & 1;

    float acc[2][8][4] = {};
    const int nk = Kp / 16;

    {   // prologue stage 0
#pragma unroll
        for (int it = 0; it < 2; it++) {
            int i = tid + it * 256;
            int r = i >> 2, c4 = (i & 3) * 4;
            size_t ga = (size_t)(row0 + r) * Kp + c4;
            cpa16(&AHs(0, r, c4), aH + ga);
            cpa16(&ALs(0, r, c4), aL + ga);
        }
#pragma unroll
        for (int it = 0; it < 2; it++) {
            int i = tid + it * 256;
            int kp = i >> 5, c4 = (i & 31) * 4;
            size_t gb = (size_t)kp * Nc + col0 + c4;
            cpa16(&BHs(0, kp, c4), wH + gb);
            cpa16(&BLs(0, kp, c4), wL + gb);
        }
        CP_COMMIT();
    }

    for (int kt = 0; kt < nk; kt++) {
        const int s = kt & 1;
        if (kt + 1 < nk) {
            const int sn = s ^ 1;
            const int k0 = (kt + 1) * 16;
#pragma unroll
            for (int it = 0; it < 2; it++) {
                int i = tid + it * 256;
                int r = i >> 2, c4 = (i & 3) * 4;
                size_t ga = (size_t)(row0 + r) * Kp + k0 + c4;
                cpa16(&AHs(sn, r, c4), aH + ga);
                cpa16(&ALs(sn, r, c4), aL + ga);
            }
#pragma unroll
            for (int it = 0; it < 2; it++) {
                int i = tid + it * 256;
                int kp = i >> 5, c4 = (i & 31) * 4;
                size_t gb = (size_t)(k0 + kp) * Nc + col0 + c4;
                cpa16(&BHs(sn, kp, c4), wH + gb);
                cpa16(&BLs(sn, kp, c4), wL + gb);
            }
            CP_COMMIT();
            CP_WAIT1();
        } else {
            CP_WAIT0();
        }
        __syncthreads();
#pragma unroll
        for (int ks = 0; ks < 2; ks++) {
            const int kb = ks * 8;
            const int kk = kb + (lane & 3);
            uint32_t aHf[2][4], aLf[2][4];
#pragma unroll
            for (int i = 0; i < 2; i++) {
                int m = wR * 32 + i * 16 + (lane >> 2);
                aHf[i][0] = AHs(s, m, kk);     aHf[i][1] = AHs(s, m + 8, kk);
                aHf[i][2] = AHs(s, m, kk + 4); aHf[i][3] = AHs(s, m + 8, kk + 4);
                aLf[i][0] = ALs(s, m, kk);     aLf[i][1] = ALs(s, m + 8, kk);
                aLf[i][2] = ALs(s, m, kk + 4); aLf[i][3] = ALs(s, m + 8, kk + 4);
            }
#pragma unroll
            for (int j = 0; j < 8; j++) {
                int n = wC * 64 + j * 8 + (lane >> 2);
                uint32_t bh0 = BHs(s, kb + (lane & 3), n);
                uint32_t bh1 = BHs(s, kb + 4 + (lane & 3), n);
                uint32_t bl0 = BLs(s, kb + (lane & 3), n);
                uint32_t bl1 = BLs(s, kb + 4 + (lane & 3), n);
#pragma unroll
                for (int i = 0; i < 2; i++) {
                    mmabf(acc[i][j], aHf[i], bh0, bh1);
                    mmabf(acc[i][j], aHf[i], bl0, bl1);
                    mmabf(acc[i][j], aLf[i], bh0, bh1);
                }
            }
        }
        __syncthreads();
    }
    // epilogue
#pragma unroll
    for (int i = 0; i < 2; i++) {
        int r = row0 + wR * 32 + i * 16 + (lane >> 2);
#pragma unroll
        for (int j = 0; j < 8; j++) {
            int c = col0 + wC * 64 + j * 8 + 2 * (lane & 3);
            float b0 = bias[c], b1 = bias[c + 1];
            float v0 = acc[i][j][0] + b0, v1 = acc[i][j][1] + b1;
            float v2 = acc[i][j][2] + b0, v3 = acc[i][j][3] + b1;
            if (act) {
                v0 = v0 / (1.0f + __expf(-v0));
                v1 = v1 / (1.0f + __expf(-v1));
                v2 = v2 / (1.0f + __expf(-v2));
                v3 = v3 / (1.0f + __expf(-v3));
            }
            if (packedOut) {
                uint32_t hh, ll;
                size_t o0 = (size_t)r * (Nc >> 1) + (c >> 1);
                split2(v0, v1, hh, ll); outH[o0] = hh; outL[o0] = ll;
                size_t o1 = (size_t)(r + 8) * (Nc >> 1) + (c >> 1);
                split2(v2, v3, hh, ll); outH[o1] = hh; outL[o1] = ll;
            } else {
                *(float2*)&outF[(size_t)r * Nc + c]       = make_float2(v0, v1);
                *(float2*)&outF[(size_t)(r + 8) * Nc + c] = make_float2(v2, v3);
            }
        }
    }
}

// =============================================================================
// Logits: dual packed-bf16x3 NT GEMM + dist/pi epilogue + dist-sum.
// Block 128(n) x 64(m), BK=16 (8 pairs), 2-stage cp.async, 72KB dyn smem.
// =============================================================================
#define QSH(s,r,c) smQsH[((s)*128 + (r))*12 + (c)]
#define QSL(s,r,c) smQsL[((s)*128 + (r))*12 + (c)]
#define QEH(s,r,c) smQeH[((s)*128 + (r))*12 + (c)]
#define QEL(s,r,c) smQeL[((s)*128 + (r))*12 + (c)]
#define KSH(s,r,c) smKsH[((s)*64 + (r))*12 + (c)]
#define KSL(s,r,c) smKsL[((s)*64 + (r))*12 + (c)]
#define KEH(s,r,c) smKeH[((s)*64 + (r))*12 + (c)]
#define KEL(s,r,c) smKeL[((s)*64 + (r))*12 + (c)]

__global__ __launch_bounds__(256) void logitsP_kernel(
    const float* __restrict__ pi_star, const float* __restrict__ gamma_p)
{
    extern __shared__ uint32_t smu[];
    uint32_t* smQsH = smu;                  // 2*128*12 = 3072 each
    uint32_t* smQsL = smQsH + 3072;
    uint32_t* smQeH = smQsL + 3072;
    uint32_t* smQeL = smQeH + 3072;
    uint32_t* smKsH = smQeL + 3072;         // 2*64*12 = 1536 each
    uint32_t* smKsL = smKsH + 1536;
    uint32_t* smKeH = smKsL + 1536;
    uint32_t* smKeL = smKeH + 1536;

    const int b  = blockIdx.z;
    const int n0 = blockIdx.y * 128;
    const int m0 = blockIdx.x * 64;
    const int tid = threadIdx.x;
    const int lane = tid & 31, warp = tid >> 5;
    const int wR = warp >> 1, wC = warp & 1;

    const uint32_t* qsH = g_qsH + (size_t)(b * Nn + n0) * 128;
    const uint32_t* qsL = g_qsL + (size_t)(b * Nn + n0) * 128;
    const uint32_t* qeH = g_qeH + (size_t)(b * Nn + n0) * 128;
    const uint32_t* qeL = g_qeL + (size_t)(b * Nn + n0) * 128;
    const uint32_t* kH  = (tid < 128) ? g_ksH + (size_t)(b * Mm + m0) * 128
                                      : g_keH + (size_t)(b * Mm + m0) * 128;
    const uint32_t* kL  = (tid < 128) ? g_ksL + (size_t)(b * Mm + m0) * 128
                                      : g_keL + (size_t)(b * Mm + m0) * 128;

    float accS[2][4][4] = {}, accE[2][4][4] = {};
    const int nk = 16;   // 128 kpairs / 8

    const int qr = tid >> 1, qc4 = (tid & 1) * 4;
    const int kt_ = tid & 127;
    const int kr = kt_ >> 1, kc4 = (kt_ & 1) * 4;
    uint32_t* dstKH = (tid < 128) ? smKsH : smKeH;
    uint32_t* dstKL = (tid < 128) ? smKsL : smKeL;

    {   // prologue
        size_t gq = (size_t)qr * 128 + qc4;
        cpa16(&QSH(0, qr, qc4), qsH + gq);
        cpa16(&QSL(0, qr, qc4), qsL + gq);
        cpa16(&QEH(0, qr, qc4), qeH + gq);
        cpa16(&QEL(0, qr, qc4), qeL + gq);
        size_t gk = (size_t)kr * 128 + kc4;
        cpa16(&dstKH[((size_t)kr) * 12 + kc4], kH + gk);
        cpa16(&dstKL[((size_t)kr) * 12 + kc4], kL + gk);
        CP_COMMIT();
    }

    for (int kt = 0; kt < nk; kt++) {
        const int s = kt & 1;
        if (kt + 1 < nk) {
            const int sn = s ^ 1;
            const int k0 = (kt + 1) * 8;
            size_t gq = (size_t)qr * 128 + k0 + qc4;
            cpa16(&QSH(sn, qr, qc4), qsH + gq);
            cpa16(&QSL(sn, qr, qc4), qsL + gq);
            cpa16(&QEH(sn, qr, qc4), qeH + gq);
            cpa16(&QEL(sn, qr, qc4), qeL + gq);
            size_t gk = (size_t)kr * 128 + k0 + kc4;
            cpa16(&dstKH[((size_t)(sn * 64 + kr)) * 12 + kc4], kH + gk);
            cpa16(&dstKL[((size_t)(sn * 64 + kr)) * 12 + kc4], kL + gk);
            CP_COMMIT();
            CP_WAIT1();
        } else {
            CP_WAIT0();
        }
        __syncthreads();
        const int kk = lane & 3;
        uint32_t asH[2][4], asL[2][4], aeH[2][4], aeL[2][4];
#pragma unroll
        for (int i = 0; i < 2; i++) {
            int m = wR * 32 + i * 16 + (lane >> 2);
            asH[i][0] = QSH(s, m, kk);     asH[i][1] = QSH(s, m + 8, kk);
            asH[i][2] = QSH(s, m, kk + 4); asH[i][3] = QSH(s, m + 8, kk + 4);
            asL[i][0] = QSL(s, m, kk);     asL[i][1] = QSL(s, m + 8, kk);
            asL[i][2] = QSL(s, m, kk + 4); asL[i][3] = QSL(s, m + 8, kk + 4);
            aeH[i][0] = QEH(s, m, kk);     aeH[i][1] = QEH(s, m + 8, kk);
            aeH[i][2] = QEH(s, m, kk + 4); aeH[i][3] = QEH(s, m + 8, kk + 4);
            aeL[i][0] = QEL(s, m, kk);     aeL[i][1] = QEL(s, m + 8, kk);
            aeL[i][2] = QEL(s, m, kk + 4); aeL[i][3] = QEL(s, m + 8, kk + 4);
        }
#pragma unroll
        for (int j = 0; j < 4; j++) {
            int n = wC * 32 + j * 8 + (lane >> 2);
            uint32_t bsh0 = KSH(s, n, kk), bsh1 = KSH(s, n, kk + 4);
            uint32_t bsl0 = KSL(s, n, kk), bsl1 = KSL(s, n, kk + 4);
            uint32_t beh0 = KEH(s, n, kk), beh1 = KEH(s, n, kk + 4);
            uint32_t bel0 = KEL(s, n, kk), bel1 = KEL(s, n, kk + 4);
#pragma unroll
            for (int i = 0; i < 2; i++) {
                mmabf(accS[i][j], asH[i], bsh0, bsh1);
                mmabf(accS[i][j], asH[i], bsl0, bsl1);
                mmabf(accS[i][j], asL[i], bsh0, bsh1);
                mmabf(accE[i][j], aeH[i], beh0, beh1);
                mmabf(accE[i][j], aeH[i], bel0, bel1);
                mmabf(accE[i][j], aeL[i], beh0, beh1);
            }
        }
        __syncthreads();
    }

    const float g = gamma_p[0];
    float sumd = 0.0f;
#pragma unroll
    for (int i = 0; i < 2; i++) {
        int n_lo = n0 + wR * 32 + i * 16 + (lane >> 2);
        float q2a = g_q2[b * Nn + n_lo];
        float q2b = g_q2[b * Nn + n_lo + 8];
#pragma unroll
        for (int j = 0; j < 4; j++) {
            int m = m0 + wC * 32 + j * 8 + 2 * (lane & 3);
            float k2a = g_k2[b * Mm + m], k2b = g_k2[b * Mm + m + 1];
            size_t base0 = ((size_t)b * Nn + n_lo) * Mm + m;
            float2 piv = *(const float2*)&pi_star[base0];
            float d0 = sqrtf(fmaxf(q2a + k2a - 2.0f * accE[i][j][0], 1e-12f));
            float d1 = sqrtf(fmaxf(q2a + k2b - 2.0f * accE[i][j][1], 1e-12f));
            sumd += d0 + d1;
            *(float2*)&g_D[base0] = make_float2(d0, d1);
            float L0 = accS[i][j][0] * 0.0625f + g * __logf(fmaxf(piv.x, 1e-9f));
            float L1 = accS[i][j][1] * 0.0625f + g * __logf(fmaxf(piv.y, 1e-9f));
            *(float2*)&g_L[base0] = make_float2(L0, L1);
            size_t base1 = ((size_t)b * Nn + n_lo + 8) * Mm + m;
            piv = *(const float2*)&pi_star[base1];
            float d2v = sqrtf(fmaxf(q2b + k2a - 2.0f * accE[i][j][2], 1e-12f));
            float d3v = sqrtf(fmaxf(q2b + k2b - 2.0f * accE[i][j][3], 1e-12f));
            sumd += d2v + d3v;
            *(float2*)&g_D[base1] = make_float2(d2v, d3v);
            float L2 = accS[i][j][2] * 0.0625f + g * __logf(fmaxf(piv.x, 1e-9f));
            float L3 = accS[i][j][3] * 0.0625f + g * __logf(fmaxf(piv.y, 1e-9f));
            *(float2*)&g_L[base1] = make_float2(L2, L3);
        }
    }
    float* red = (float*)smu;
    red[tid] = sumd;
    __syncthreads();
    for (int sred = 128; sred > 0; sred >>= 1) {
        if (tid < sred) red[tid] += red[tid + sred];
        __syncthreads();
    }
    if (tid == 0) atomicAdd(&g_dsum[b], red[0]);
}

// =============================================================================
// Ctx: dual packed-bf16x3 NN GEMM attn@Vs / attn@Ve -> fused packed features.
// Block 128(n) x 64(h), BK=32 (16 pairs), 2-stage cp.async, 80KB dyn smem.
// =============================================================================
#define PHs(s,r,c)  smPH[((s)*128 + (r))*20 + (c)]
#define PLs(s,r,c)  smPL[((s)*128 + (r))*20 + (c)]
#define VSH(s,h,c)  smVsH[((s)*64 + (h))*20 + (c)]
#define VSL(s,h,c)  smVsL[((s)*64 + (h))*20 + (c)]
#define VEH(s,h,c)  smVeH[((s)*64 + (h))*20 + (c)]
#define VEL(s,h,c)  smVeL[((s)*64 + (h))*20 + (c)]

__global__ __launch_bounds__(256) void ctxP_kernel()
{
    extern __shared__ uint32_t smu[];
    uint32_t* smPH  = smu;                  // 2*128*20 = 5120
    uint32_t* smPL  = smPH + 5120;
    uint32_t* smVsH = smPL + 5120;          // 2*64*20 = 2560 each
    uint32_t* smVsL = smVsH + 2560;
    uint32_t* smVeH = smVsL + 2560;
    uint32_t* smVeL = smVeH + 2560;

    const int b  = blockIdx.z;
    const int n0 = blockIdx.y * 128;
    const int h0 = blockIdx.x * 64;
    const int tid = threadIdx.x;
    const int lane = tid & 31, warp = tid >> 5;
    const int wR = warp >> 1, wC = warp & 1;

    const uint32_t* pH = g_pH + (size_t)(b * Nn + n0) * 1024;
    const uint32_t* pL = g_pL + (size_t)(b * Nn + n0) * 1024;
    const uint32_t* vsH = g_vsTH + ((size_t)b * Hh + h0) * 1024;
    const uint32_t* vsL = g_vsTL + ((size_t)b * Hh + h0) * 1024;
    const uint32_t* veH = g_veTH + ((size_t)b * Hh + h0) * 1024;
    const uint32_t* veL = g_veTL + ((size_t)b * Hh + h0) * 1024;

    float accS[2][4][4] = {}, accE[2][4][4] = {};
    const int nk = 64;   // 1024 mpairs / 16

    {   // prologue
#pragma unroll
        for (int it = 0; it < 2; it++) {
            int i = tid + it * 256;
            int r = i >> 2, c4 = (i & 3) * 4;
            size_t gp = (size_t)r * 1024 + c4;
            cpa16(&PHs(0, r, c4), pH + gp);
            cpa16(&PLs(0, r, c4), pL + gp);
        }
        {
            int h = tid >> 2, c4 = (tid & 3) * 4;
            size_t gv = (size_t)h * 1024 + c4;
            cpa16(&VSH(0, h, c4), vsH + gv);
            cpa16(&VSL(0, h, c4), vsL + gv);
            cpa16(&VEH(0, h, c4), veH + gv);
            cpa16(&VEL(0, h, c4), veL + gv);
        }
        CP_COMMIT();
    }

    for (int kt = 0; kt < nk; kt++) {
        const int s = kt & 1;
        if (kt + 1 < nk) {
            const int sn = s ^ 1;
            const int mp0 = (kt + 1) * 16;
#pragma unroll
            for (int it = 0; it < 2; it++) {
                int i = tid + it * 256;
                int r = i >> 2, c4 = (i & 3) * 4;
                size_t gp = (size_t)r * 1024 + mp0 + c4;
                cpa16(&PHs(sn, r, c4), pH + gp);
                cpa16(&PLs(sn, r, c4), pL + gp);
            }
            {
                int h = tid >> 2, c4 = (tid & 3) * 4;
                size_t gv = (size_t)h * 1024 + mp0 + c4;
                cpa16(&VSH(sn, h, c4), vsH + gv);
                cpa16(&VSL(sn, h, c4), vsL + gv);
                cpa16(&VEH(sn, h, c4), veH + gv);
                cpa16(&VEL(sn, h, c4), veL + gv);
            }
            CP_COMMIT();
            CP_WAIT1();
        } else {
            CP_WAIT0();
        }
        __syncthreads();
#pragma unroll
        for (int ks = 0; ks < 2; ks++) {
            const int kb = ks * 8;
            const int kk = kb + (lane & 3);
            uint32_t aHf[2][4], aLf[2][4];
#pragma unroll
            for (int i = 0; i < 2; i++) {
                int m = wR * 32 + i * 16 + (lane >> 2);
                aHf[i][0] = PHs(s, m, kk);     aHf[i][1] = PHs(s, m + 8, kk);
                aHf[i][2] = PHs(s, m, kk + 4); aHf[i][3] = PHs(s, m + 8, kk + 4);
                aLf[i][0] = PLs(s, m, kk);     aLf[i][1] = PLs(s, m + 8, kk);
                aLf[i][2] = PLs(s, m, kk + 4); aLf[i][3] = PLs(s, m + 8, kk + 4);
            }
#pragma unroll
            for (int j = 0; j < 4; j++) {
                int h = wC * 32 + j * 8 + (lane >> 2);
                uint32_t sh0 = VSH(s, h, kk), sh1 = VSH(s, h, kk + 4);
                uint32_t sl0 = VSL(s, h, kk), sl1 = VSL(s, h, kk + 4);
                uint32_t eh0 = VEH(s, h, kk), eh1 = VEH(s, h, kk + 4);
                uint32_t el0 = VEL(s, h, kk), el1 = VEL(s, h, kk + 4);
#pragma unroll
                for (int i = 0; i < 2; i++) {
                    mmabf(accS[i][j], aHf[i], sh0, sh1);
                    mmabf(accS[i][j], aHf[i], sl0, sl1);
                    mmabf(accS[i][j], aLf[i], sh0, sh1);
                    mmabf(accE[i][j], aHf[i], eh0, eh1);
                    mmabf(accE[i][j], aHf[i], el0, el1);
                    mmabf(accE[i][j], aLf[i], eh0, eh1);
                }
            }
        }
        __syncthreads();
    }
    // fused packed epilogue: sections [cs | ce | cs-ce | cs*ce] along 4H
#pragma unroll
    for (int i = 0; i < 2; i++) {
        int n_lo = n0 + wR * 32 + i * 16 + (lane >> 2);
#pragma unroll
        for (int j = 0; j < 4; j++) {
            int h = h0 + wC * 32 + j * 8 + 2 * (lane & 3);
#pragma unroll
            for (int half = 0; half < 2; half++) {
                int n = n_lo + half * 8;
                float cs0 = accS[i][j][half * 2 + 0], cs1 = accS[i][j][half * 2 + 1];
                float ce0 = accE[i][j][half * 2 + 0], ce1 = accE[i][j][half * 2 + 1];
                size_t fb = ((size_t)b * Nn + n) * 512;
                uint32_t hh, ll;
                split2(cs0, cs1, hh, ll);
                g_fH[fb + (h >> 1)] = hh;             g_fL[fb + (h >> 1)] = ll;
                split2(ce0, ce1, hh, ll);
                g_fH[fb + 128 + (h >> 1)] = hh;       g_fL[fb + 128 + (h >> 1)] = ll;
                split2(cs0 - ce0, cs1 - ce1, hh, ll);
                g_fH[fb + 256 + (h >> 1)] = hh;       g_fL[fb + 256 + (h >> 1)] = ll;
                split2(cs0 * ce0, cs1 * ce1, hh, ll);
                g_fH[fb + 384 + (h >> 1)] = hh;       g_fL[fb + 384 + (h >> 1)] = ll;
            }
        }
    }
}

// ---------------- softmax: 256 thr/row, 8 consecutive cols per thread -------
__global__ void softmax_kernel(const float* __restrict__ ew_p) {
    const int row = blockIdx.x;
    const int b   = row / Nn;
    const float invsc = ew_p[0] / g_scale[b];
    const size_t base = (size_t)row * Mm;
    const int c0 = threadIdx.x * 8;
    float v[8];
    float mx = -1e30f;
#pragma unroll
    for (int q = 0; q < 2; q++) {
        float4 lv = *(const float4*)&g_L[base + c0 + q * 4];
        float4 dv = *(const float4*)&g_D[base + c0 + q * 4];
        v[q*4+0] = lv.x - dv.x * invsc; v[q*4+1] = lv.y - dv.y * invsc;
        v[q*4+2] = lv.z - dv.z * invsc; v[q*4+3] = lv.w - dv.w * invsc;
    }
#pragma unroll
    for (int t = 0; t < 8; t++) mx = fmaxf(mx, v[t]);
    __shared__ float sh[8];
    __shared__ float bc;
    int lane = threadIdx.x & 31, wid = threadIdx.x >> 5;
    float wm = warpRedMax(mx);
    if (lane == 0) sh[wid] = wm;
    __syncthreads();
    if (wid == 0) {
        float t = (lane < 8) ? sh[lane] : -1e30f;
        t = warpRedMax(t);
        if (lane == 0) bc = t;
    }
    __syncthreads();
    mx = bc;
    float sum = 0.0f;
#pragma unroll
    for (int t = 0; t < 8; t++) {
        v[t] = __expf(v[t] - mx);
        sum += v[t];
    }
    __syncthreads();
    float ws = warpRedSum(sum);
    if (lane == 0) sh[wid] = ws;
    __syncthreads();
    if (wid == 0) {
        float t = (lane < 8) ? sh[lane] : 0.0f;
        t = warpRedSum(t);
        if (lane == 0) bc = t;
    }
    __syncthreads();
    const float inv = 1.0f / bc;
    const size_t pbase = (size_t)row * 1024 + threadIdx.x * 4;
#pragma unroll
    for (int p = 0; p < 4; p++) {
        uint32_t hh, ll;
        split2(v[2 * p] * inv, v[2 * p + 1] * inv, hh, ll);
        g_pH[pbase + p] = hh; g_pL[pbase + p] = ll;
    }
}

// ---------------- launch ----------------
extern "C" void kernel_launch(void* const* d_in, const int* in_sizes, int n_in,
                              void* d_out, int out_size) {
    const float* q_fp  = (const float*)d_in[0];
    const float* v_ret = (const float*)d_in[1];
    const float* pi    = (const float*)d_in[2];
    const float* Wqs = (const float*)d_in[3];  const float* bqs = (const float*)d_in[4];
    const float* Wks = (const float*)d_in[5];  const float* bks = (const float*)d_in[6];
    const float* Wvs = (const float*)d_in[7];  const float* bvs = (const float*)d_in[8];
    const float* Wqe = (const float*)d_in[9];  const float* bqe = (const float*)d_in[10];
    const float* Wke = (const float*)d_in[11]; const float* bke = (const float*)d_in[12];
    const float* Wve = (const float*)d_in[13]; const float* bve = (const float*)d_in[14];
    const float* W1  = (const float*)d_in[15]; const float* b1  = (const float*)d_in[16];
    const float* W2  = (const float*)d_in[17]; const float* b2  = (const float*)d_in[18];
    const float* gamma = (const float*)d_in[19];
    const float* ew    = (const float*)d_in[20];
    float* out = (float*)d_out;

    uint32_t *qfH, *qfL, *vrH, *vrL, *wH, *wL;
    uint32_t *qsH, *qsL, *qeH, *qeL, *ksH, *ksL, *keH, *keL;
    uint32_t *vsTH, *vsTL, *veTH, *veTL, *fH, *fL, *hH, *hL;
    float *vs_p, *ve_p, *q2_p, *k2_p;
    cudaGetSymbolAddress((void**)&qfH, g_qfH); cudaGetSymbolAddress((void**)&qfL, g_qfL);
    cudaGetSymbolAddress((void**)&vrH, g_vrH); cudaGetSymbolAddress((void**)&vrL, g_vrL);
    cudaGetSymbolAddress((void**)&wH, g_wH);   cudaGetSymbolAddress((void**)&wL, g_wL);
    cudaGetSymbolAddress((void**)&qsH, g_qsH); cudaGetSymbolAddress((void**)&qsL, g_qsL);
    cudaGetSymbolAddress((void**)&qeH, g_qeH); cudaGetSymbolAddress((void**)&qeL, g_qeL);
    cudaGetSymbolAddress((void**)&ksH, g_ksH); cudaGetSymbolAddress((void**)&ksL, g_ksL);
    cudaGetSymbolAddress((void**)&keH, g_keH); cudaGetSymbolAddress((void**)&keL, g_keL);
    cudaGetSymbolAddress((void**)&vsTH, g_vsTH); cudaGetSymbolAddress((void**)&vsTL, g_vsTL);
    cudaGetSymbolAddress((void**)&veTH, g_veTH); cudaGetSymbolAddress((void**)&veTL, g_veTL);
    cudaGetSymbolAddress((void**)&fH, g_fH);   cudaGetSymbolAddress((void**)&fL, g_fL);
    cudaGetSymbolAddress((void**)&hH, g_hH);   cudaGetSymbolAddress((void**)&hL, g_hL);
    cudaGetSymbolAddress((void**)&vs_p, g_vs); cudaGetSymbolAddress((void**)&ve_p, g_ve);
    cudaGetSymbolAddress((void**)&q2_p, g_q2); cudaGetSymbolAddress((void**)&k2_p, g_k2);

    const int GEMM_SMEM   = (5120 * 2 + 4352 * 2) * 4;                // 75776
    const int LOGIT_SMEM  = (3072 * 4 + 1536 * 4) * 4;                // 73728
    const int CTX_SMEM    = (5120 * 2 + 2560 * 4) * 4;                // 81920
    cudaFuncSetAttribute(gemmP_kernel,  cudaFuncAttributeMaxDynamicSharedMemorySize, GEMM_SMEM);
    cudaFuncSetAttribute(logitsP_kernel, cudaFuncAttributeMaxDynamicSharedMemorySize, LOGIT_SMEM);
    cudaFuncSetAttribute(ctxP_kernel,   cudaFuncAttributeMaxDynamicSharedMemorySize, CTX_SMEM);

    // ---- pack inputs & weights ----
    pack_rows_kernel<<<(Bb*Nn*DIN/2 + 255)/256, 256>>>(q_fp,  qfH, qfL, Bb*Nn*DIN/2);
    pack_rows_kernel<<<(Bb*Mm*DIN/2 + 255)/256, 256>>>(v_ret, vrH, vrL, Bb*Mm*DIN/2);
    uint32_t* wHo[8] = {wH, wH+65536, wH+131072, wH+196608, wH+262144, wH+327680,
                        wH+393216, wH+524288};
    uint32_t* wLo[8] = {wL, wL+65536, wL+131072, wL+196608, wL+262144, wL+327680,
                        wL+393216, wL+524288};
    const float* Ws[8] = {Wqs, Wks, Wvs, Wqe, Wke, Wve, W1, W2};
    const int   Kps[8] = {256, 256, 256, 256, 256, 256, 512, 128};
    for (int w = 0; w < 8; w++)
        pack_weight_kernel<<<(Kps[w]*256 + 255)/256, 256>>>(Ws[w], wHo[w], wLo[w], Kps[w], 256);

    // ---- projections ----
    dim3 gp(2, (Bb * Nn) / 128);
    gemmP_kernel<<<gp, 256, GEMM_SMEM>>>(qfH, qfL, wHo[0], wLo[0], bqs, nullptr, qsH, qsL, 256, 256, 0, 1);
    gemmP_kernel<<<gp, 256, GEMM_SMEM>>>(vrH, vrL, wHo[1], wLo[1], bks, nullptr, ksH, ksL, 256, 256, 0, 1);
    gemmP_kernel<<<gp, 256, GEMM_SMEM>>>(vrH, vrL, wHo[2], wLo[2], bvs, vs_p, nullptr, nullptr, 256, 256, 0, 0);
    gemmP_kernel<<<gp, 256, GEMM_SMEM>>>(qfH, qfL, wHo[3], wLo[3], bqe, nullptr, qeH, qeL, 256, 256, 0, 1);
    gemmP_kernel<<<gp, 256, GEMM_SMEM>>>(vrH, vrL, wHo[4], wLo[4], bke, nullptr, keH, keL, 256, 256, 0, 1);
    gemmP_kernel<<<gp, 256, GEMM_SMEM>>>(vrH, vrL, wHo[5], wLo[5], bve, ve_p, nullptr, nullptr, 256, 256, 0, 0);

    dim3 gt(Mm / 64, Hh / 32, Bb);
    transpose_pack_kernel<<<gt, 256>>>(vs_p, vsTH, vsTL);
    transpose_pack_kernel<<<gt, 256>>>(ve_p, veTH, veTL);

    rowsumsq_kernel<<<Bb * Nn, 128>>>(qeH, qeL, q2_p);
    rowsumsq_kernel<<<Bb * Mm, 128>>>(keH, keL, k2_p);

    zero_dsum_kernel<<<1, 32>>>();
    dim3 gl(Mm / 64, Nn / 128, Bb);
    logitsP_kernel<<<gl, 256, LOGIT_SMEM>>>(pi, gamma);
    finalize_scale_kernel<<<1, 32>>>();

    softmax_kernel<<<Bb * Nn, 256>>>(ew);

    dim3 gc(Hh / 64, Nn / 128, Bb);
    ctxP_kernel<<<gc, 256, CTX_SMEM>>>();

    // ---- MLP ----
    dim3 gm(2, (Bb * Nn) / 128);
    gemmP_kernel<<<gm, 256, GEMM_SMEM>>>(fH, fL, wHo[6], wLo[6], b1, nullptr, hH, hL, 512, 256, 1, 1);
    gemmP_kernel<<<gm, 256, GEMM_SMEM>>>(hH, hL, wHo[7], wLo[7], b2, out, nullptr, nullptr, 128, 256, 0, 0);
}